// round 10
// baseline (speedup 1.0000x reference)
#include <cuda_runtime.h>
#include <cstdint>

// ---------------- problem constants ----------------
constexpr int B    = 8;
constexpr int C    = 5;
constexpr int NN   = 512;
constexpr int FIN  = 768;
constexpr int H    = 4;
constexpr int DHID = 128;
constexpr int DOUT = 64;
constexpr int HD   = H * DHID;   // 512
constexpr int HD2  = H * DOUT;   // 256
constexpr int BC   = B * C;      // 40

// ---------------- scratch ----------------
__device__ __align__(256) float g_feat[(size_t)BC * NN * HD];   // gemm out (f32), agg in
__device__ __align__(256) float g_hhi [(size_t)BC * NN * HD];   // agg out, hi plane
__device__ __align__(256) float g_hlo [(size_t)BC * NN * HD];   // agg out, lo plane
__device__ __align__(256) float g_xhi [(size_t)B * NN * FIN];   // x[:,0] hi plane
__device__ __align__(256) float g_xlo [(size_t)B * NN * FIN];   // x[:,0] lo plane
__device__ __align__(256) float g_out2[(size_t)BC * NN * HD2];
__device__ __align__(256) float g_el  [BC * H * NN];
__device__ __align__(256) float g_er  [BC * H * NN];

// ---------------- gemm smem geometry ----------------
constexpr int AP = 20;
constexpr int BP = 136;
constexpr int A_STG = 128 * AP;            // per plane
constexpr int B_STG = 16 * BP;
constexpr int STG   = 2 * A_STG + B_STG;   // Ahi | Alo | B
constexpr int GEMM_SMEM = 3 * STG * 4;     // 87552 B

__device__ __forceinline__ uint32_t f2tf32(float f) {
    uint32_t u;
    asm("cvt.rna.tf32.f32 %0, %1;" : "=r"(u) : "f"(f));
    return u;
}

__device__ __forceinline__ void mma_tf32(float* d, const uint32_t* a, const uint32_t* b) {
    asm volatile(
        "mma.sync.aligned.m16n8k8.row.col.f32.tf32.tf32.f32 "
        "{%0,%1,%2,%3}, {%4,%5,%6,%7}, {%8,%9}, {%0,%1,%2,%3};\n"
        : "+f"(d[0]), "+f"(d[1]), "+f"(d[2]), "+f"(d[3])
        : "r"(a[0]), "r"(a[1]), "r"(a[2]), "r"(a[3]), "r"(b[0]), "r"(b[1]));
}

__device__ __forceinline__ void cp16(uint32_t smem_dst, const float* gsrc) {
    asm volatile("cp.async.ca.shared.global [%0], [%1], 16;\n"
                 :: "r"(smem_dst), "l"(gsrc));
}

__device__ __forceinline__ uint32_t ldu32(const float* p) {
    return __float_as_uint(*p);
}

// ---------------- x pre-split: x[:,0] -> hi/lo tf32 planes ----------------
__global__ void split_x(const float* __restrict__ x,
                        float* __restrict__ hi, float* __restrict__ lo) {
    int idx = blockIdx.x * 256 + threadIdx.x;
    if (idx >= B * NN * FIN) return;
    int b = idx / (NN * FIN);
    int off = idx - b * (NN * FIN);
    float v = x[(size_t)b * C * NN * FIN + off];
    uint32_t h = f2tf32(v);
    hi[idx] = __uint_as_float(h);
    lo[idx] = __uint_as_float(f2tf32(v - __uint_as_float(h)));
}

// ---------------- tf32 GEMM: pre-split A planes, runtime-split W, fused el/er ----------
__global__ __launch_bounds__(256, 2) void gemm_tc(
    const float* __restrict__ Ahi, const float* __restrict__ Alo,
    const float* __restrict__ W,
    float* __restrict__ Co, int K, int Nn, size_t aSB, size_t aSC,
    const float* __restrict__ al, const float* __restrict__ ar,
    float* __restrict__ elo, float* __restrict__ ero, int Dh) {
    extern __shared__ float sm[];

    int bc = blockIdx.z;
    int b  = bc / C, c = bc % C;
    const float* AbH = Ahi + (size_t)b * aSB + (size_t)c * aSC;
    const float* AbL = Alo + (size_t)b * aSB + (size_t)c * aSC;
    const float* Wc  = W + (size_t)c * K * Nn;
    float*       Cb  = Co + (size_t)bc * NN * Nn;

    int m0 = blockIdx.y * 128, n0 = blockIdx.x * 128;
    int tid  = threadIdx.x;
    int lane = tid & 31, warp = tid >> 5;
    int wm = warp & 1, wn = warp >> 1;
    int gr = lane >> 2, tg = lane & 3;

    uint32_t smem_base = (uint32_t)__cvta_generic_to_shared(sm);

    int am0 = tid >> 2,          akq = (tid & 3) * 4;
    int am1 = (tid + 256) >> 2;
    int bk0 = tid >> 5,          bnq = (tid & 31) * 4;
    int bk1 = (tid + 256) >> 5;

    auto issue_stage = [&](int st, int t) {
        uint32_t hB = smem_base + (st * STG) * 4;
        uint32_t lB = hB + A_STG * 4;
        uint32_t bB = lB + A_STG * 4;
        size_t aoff = (size_t)m0 * K + t * 16 + akq;
        cp16(hB + (am0 * AP + akq) * 4, AbH + aoff + (size_t)am0 * K);
        cp16(hB + (am1 * AP + akq) * 4, AbH + aoff + (size_t)am1 * K);
        cp16(lB + (am0 * AP + akq) * 4, AbL + aoff + (size_t)am0 * K);
        cp16(lB + (am1 * AP + akq) * 4, AbL + aoff + (size_t)am1 * K);
        const float* Wct = Wc + (size_t)(t * 16) * Nn + n0;
        cp16(bB + (bk0 * BP + bnq) * 4, Wct + (size_t)bk0 * Nn + bnq);
        cp16(bB + (bk1 * BP + bnq) * 4, Wct + (size_t)bk1 * Nn + bnq);
    };

    float acc[4][4][4] = {};

    auto compute_stage = [&](int st) {
        const float* AhS = sm + st * STG;
        const float* AlS = AhS + A_STG;
        const float* Bs  = AlS + A_STG;
#pragma unroll
        for (int ks = 0; ks < 16; ks += 8) {
            int kA = ks + tg;
            uint32_t ah[4][4], al_[4][4], bh[4][2], bl[4][2];
#pragma unroll
            for (int mt = 0; mt < 4; mt++) {
                int m = wm * 64 + mt * 16 + gr;
                ah[mt][0]  = ldu32(AhS + m * AP + kA);
                ah[mt][1]  = ldu32(AhS + (m + 8) * AP + kA);
                ah[mt][2]  = ldu32(AhS + m * AP + kA + 4);
                ah[mt][3]  = ldu32(AhS + (m + 8) * AP + kA + 4);
                al_[mt][0] = ldu32(AlS + m * AP + kA);
                al_[mt][1] = ldu32(AlS + (m + 8) * AP + kA);
                al_[mt][2] = ldu32(AlS + m * AP + kA + 4);
                al_[mt][3] = ldu32(AlS + (m + 8) * AP + kA + 4);
            }
#pragma unroll
            for (int nt = 0; nt < 4; nt++) {
                int n = wn * 32 + nt * 8 + gr;
                float w0 = Bs[kA * BP + n];
                float w1 = Bs[(kA + 4) * BP + n];
                bh[nt][0] = f2tf32(w0); bl[nt][0] = f2tf32(w0 - __uint_as_float(bh[nt][0]));
                bh[nt][1] = f2tf32(w1); bl[nt][1] = f2tf32(w1 - __uint_as_float(bh[nt][1]));
            }
#pragma unroll
            for (int mt = 0; mt < 4; mt++)
#pragma unroll
                for (int nt = 0; nt < 4; nt++) {
                    mma_tf32(acc[mt][nt], ah[mt], bh[nt]);
                    mma_tf32(acc[mt][nt], al_[mt], bh[nt]);
                    mma_tf32(acc[mt][nt], ah[mt], bl[nt]);
                }
        }
    };

    int T = K / 16;
    issue_stage(0, 0);
    asm volatile("cp.async.commit_group;\n" ::);
    issue_stage(1, 1);
    asm volatile("cp.async.commit_group;\n" ::);

    for (int i = 0; i < T; i++) {
        asm volatile("cp.async.wait_group 1;\n" ::);
        __syncthreads();
        if (i + 2 < T) issue_stage((i + 2) % 3, i + 2);
        asm volatile("cp.async.commit_group;\n" ::);
        compute_stage(i % 3);
    }

    // ---- epilogue: store C + fused el/er partials ----
    int head  = (n0 + wn * 32) / Dh;
    int dbase = n0 + wn * 32 - head * Dh;
    const float* alh = al + ((size_t)c * H + head) * Dh;
    const float* arh = ar + ((size_t)c * H + head) * Dh;
    float* elh = elo + ((size_t)bc * H + head) * NN;
    float* erh = ero + ((size_t)bc * H + head) * NN;

#pragma unroll
    for (int mt = 0; mt < 4; mt++) {
        float el0 = 0.f, el1 = 0.f, er0 = 0.f, er1 = 0.f;
#pragma unroll
        for (int nt = 0; nt < 4; nt++) {
            int row = m0 + wm * 64 + mt * 16 + gr;
            int col = n0 + wn * 32 + nt * 8 + tg * 2;
            *(float2*)(Cb + (size_t)row * Nn + col) =
                make_float2(acc[mt][nt][0], acc[mt][nt][1]);
            *(float2*)(Cb + (size_t)(row + 8) * Nn + col) =
                make_float2(acc[mt][nt][2], acc[mt][nt][3]);

            int d = dbase + nt * 8 + tg * 2;
            float a0 = alh[d], a1 = alh[d + 1];
            float r0 = arh[d], r1 = arh[d + 1];
            el0 += acc[mt][nt][0] * a0 + acc[mt][nt][1] * a1;
            el1 += acc[mt][nt][2] * a0 + acc[mt][nt][3] * a1;
            er0 += acc[mt][nt][0] * r0 + acc[mt][nt][1] * r1;
            er1 += acc[mt][nt][2] * r0 + acc[mt][nt][3] * r1;
        }
#pragma unroll
        for (int o = 1; o < 4; o <<= 1) {
            el0 += __shfl_xor_sync(0xffffffffu, el0, o);
            el1 += __shfl_xor_sync(0xffffffffu, el1, o);
            er0 += __shfl_xor_sync(0xffffffffu, er0, o);
            er1 += __shfl_xor_sync(0xffffffffu, er1, o);
        }
        if (tg == 0) {
            int row = m0 + wm * 64 + mt * 16 + gr;
            atomicAdd(elh + row,     el0);
            atomicAdd(elh + row + 8, el1);
            atomicAdd(erh + row,     er0);
            atomicAdd(erh + row + 8, er1);
        }
    }
}

// ================= agg v2 (D=128, JT=128): produce-ahead, pre-cvt p, hi/lo output ========
// SPLIT_OUT: write hi/lo tf32 planes (for next-layer gemm) instead of single f32.
template <bool RELU>
__global__ __launch_bounds__(256, 2) void agg_tc2(
    const float* __restrict__ adj,
    const float* __restrict__ feat,
    const float* __restrict__ el,
    const float* __restrict__ er,
    const float* __restrict__ bias,
    float* __restrict__ outHi,
    float* __restrict__ outLo) {
    constexpr int D  = 128, JT = 128;
    constexpr int PP = JT + 8;
    constexpr int FP = D + 8;
    constexpr int NSUB = 256 / JT;
    constexpr int ADJ_ST = 16 * JT;
    constexpr int F_ST   = 16 * FP;
    constexpr int P_ST   = 16 * PP;
    constexpr int T = NN / 16;

    extern __shared__ float sm[];
    float* el_s  = sm;
    float* er_s  = el_s + NN;
    float* m_s   = er_s + JT;
    float* sc_s  = m_s + JT;
    float* red   = sc_s + JT;
    float* s_red = red + 8;
    float* adj_s = s_red + NSUB * JT;
    float* f_s   = adj_s + 4 * ADJ_ST;
    float* p_s   = f_s + 4 * F_ST;

    int bc = blockIdx.z, h = blockIdx.y;
    int c = bc % C;
    int j0 = blockIdx.x * JT;
    int tid = threadIdx.x;
    int lane = tid & 31, warp = tid >> 5;
    int jm = warp & 1, dn = warp >> 1;
    int gr = lane >> 2, tg = lane & 3;

    const float* adj_bc = adj + (size_t)bc * NN * NN;
    const float* elh = el + (size_t)(bc * H + h) * NN;
    const float* erh = er + (size_t)(bc * H + h) * NN;
    const float* featb = feat + (size_t)bc * NN * (H * D) + h * D;

    uint32_t smem_u32 = (uint32_t)__cvta_generic_to_shared(sm);
    uint32_t adj_u32  = smem_u32 + (uint32_t)((adj_s - sm) * 4);
    uint32_t f_u32    = smem_u32 + (uint32_t)((f_s - sm) * 4);

    auto issue_stage = [&](int st, int t) {
        uint32_t aB = adj_u32 + st * ADJ_ST * 4;
#pragma unroll
        for (int l = 0; l < (16 * JT / 4) / 256; l++) {
            int s = tid + l * 256;
            int r = s / (JT / 4), cq = s % (JT / 4);
            cp16(aB + (r * JT + cq * 4) * 4,
                 adj_bc + (size_t)(t * 16 + r) * NN + j0 + cq * 4);
        }
        uint32_t fB = f_u32 + st * F_ST * 4;
#pragma unroll
        for (int l = 0; l < (16 * D / 4) / 256; l++) {
            int s = tid + l * 256;
            int r = s / (D / 4), cq = s % (D / 4);
            cp16(fB + (r * FP + cq * 4) * 4,
                 featb + (size_t)(t * 16 + r) * (H * D) + cq * 4);
        }
    };

    float e0 = elh[tid], e1 = elh[tid + 256];
    el_s[tid] = e0; el_s[tid + 256] = e1;
    if (tid < JT) er_s[tid] = erh[j0 + tid];

    issue_stage(0, 0);
    asm volatile("cp.async.commit_group;\n" ::);
    issue_stage(1, 1);
    asm volatile("cp.async.commit_group;\n" ::);
    issue_stage(2, 2);
    asm volatile("cp.async.commit_group;\n" ::);

    float v = fmaxf(e0, e1);
#pragma unroll
    for (int o = 16; o; o >>= 1) v = fmaxf(v, __shfl_xor_sync(0xffffffffu, v, o));
    if (lane == 0) red[warp] = v;
    __syncthreads();
    if (tid == 0) {
        float m = red[0];
#pragma unroll
        for (int w = 1; w < 8; w++) m = fmaxf(m, red[w]);
        red[0] = m;
    }
    __syncthreads();
    if (tid < JT) {
        float e = red[0] + er_s[tid];
        m_s[tid] = e > 0.f ? e : 0.2f * e;
    }

    int pj  = tid % JT;
    int pi0 = tid / JT;
    float s_priv = 0.f;

    // produce p(t) PRE-CONVERTED to tf32 bits
    auto produce = [&](int t) {
        const float* a_st = adj_s + (t % 4) * ADJ_ST;
        float* p_nb = p_s + (t & 1) * P_ST;
#pragma unroll
        for (int q = 0; q < 16 / NSUB; q++) {
            int r = pi0 + q * NSUB;
            float a = a_st[r * JT + pj];
            float pt = 0.f;
            if (a > 0.f) {
                float e = el_s[t * 16 + r] + er_s[pj];
                e = e > 0.f ? e : 0.2f * e;
                float p = __expf(e - m_s[pj]);
                pt = __uint_as_float(f2tf32(p));
                s_priv += pt;
            }
            p_nb[r * PP + pj] = pt;
        }
    };

    asm volatile("cp.async.wait_group 2;\n" ::);
    __syncthreads();
    produce(0);

    float acc[4][4][4] = {};

    for (int i = 0; i < T; i++) {
        asm volatile("cp.async.wait_group 1;\n" ::);
        __syncthreads();

        const float* f_st  = f_s + (i % 4) * F_ST;
        const float* p_buf = p_s + (i & 1) * P_ST;
#pragma unroll
        for (int ks = 0; ks < 16; ks += 8) {
            int kA = ks + tg;
            uint32_t ah[4][4];
#pragma unroll
            for (int mt = 0; mt < 4; mt++) {
                int jb = jm * 64 + mt * 16 + gr;
                ah[mt][0] = ldu32(p_buf + kA * PP + jb);
                ah[mt][1] = ldu32(p_buf + kA * PP + jb + 8);
                ah[mt][2] = ldu32(p_buf + (kA + 4) * PP + jb);
                ah[mt][3] = ldu32(p_buf + (kA + 4) * PP + jb + 8);
            }
#pragma unroll
            for (int nt = 0; nt < 4; nt++) {
                int db = dn * 32 + nt * 8 + gr;
                float w0 = f_st[kA * FP + db];
                float w1 = f_st[(kA + 4) * FP + db];
                uint32_t bh[2], bl[2];
                bh[0] = f2tf32(w0); bl[0] = f2tf32(w0 - __uint_as_float(bh[0]));
                bh[1] = f2tf32(w1); bl[1] = f2tf32(w1 - __uint_as_float(bh[1]));
#pragma unroll
                for (int mt = 0; mt < 4; mt++) {
                    mma_tf32(acc[mt][nt], ah[mt], bh);
                    mma_tf32(acc[mt][nt], ah[mt], bl);
                }
            }
        }

        if (i + 1 < T) produce(i + 1);

        if (i + 3 < T) issue_stage((i + 3) % 4, i + 3);
        asm volatile("cp.async.commit_group;\n" ::);
    }

    s_red[pi0 * JT + pj] = s_priv;
    __syncthreads();
    if (tid < JT)
        sc_s[tid] = 1.0f / fmaxf(s_red[tid] + s_red[JT + tid], 1e-9f);
    __syncthreads();

    const float* bh_ = bias + (size_t)c * (H * D) + h * D;
#pragma unroll
    for (int mt = 0; mt < 4; mt++) {
#pragma unroll
        for (int nt = 0; nt < 4; nt++) {
            int jl = jm * 64 + mt * 16 + gr;
            int d  = dn * 32 + nt * 8 + tg * 2;
            float bb0 = bh_[d], bb1 = bh_[d + 1];
            float sc0 = sc_s[jl], sc1 = sc_s[jl + 8];
            float o0 = acc[mt][nt][0] * sc0 + bb0;
            float o1 = acc[mt][nt][1] * sc0 + bb1;
            float o2 = acc[mt][nt][2] * sc1 + bb0;
            float o3 = acc[mt][nt][3] * sc1 + bb1;
            if (RELU) {
                o0 = fmaxf(o0, 0.f); o1 = fmaxf(o1, 0.f);
                o2 = fmaxf(o2, 0.f); o3 = fmaxf(o3, 0.f);
            }
            // split into hi/lo tf32 planes (identical to split-at-load numerics)
            uint32_t h0 = f2tf32(o0), h1 = f2tf32(o1), h2 = f2tf32(o2), h3 = f2tf32(o3);
            float l0 = __uint_as_float(f2tf32(o0 - __uint_as_float(h0)));
            float l1 = __uint_as_float(f2tf32(o1 - __uint_as_float(h1)));
            float l2 = __uint_as_float(f2tf32(o2 - __uint_as_float(h2)));
            float l3 = __uint_as_float(f2tf32(o3 - __uint_as_float(h3)));
            int j = j0 + jl;
            size_t off0 = ((size_t)bc * NN + j) * (H * D) + h * D + d;
            size_t off1 = ((size_t)bc * NN + j + 8) * (H * D) + h * D + d;
            *(float2*)(outHi + off0) = make_float2(__uint_as_float(h0), __uint_as_float(h1));
            *(float2*)(outHi + off1) = make_float2(__uint_as_float(h2), __uint_as_float(h3));
            *(float2*)(outLo + off0) = make_float2(l0, l1);
            *(float2*)(outLo + off1) = make_float2(l2, l3);
        }
    }
}

constexpr int AGG2_SMEM = (NN + 3 * 128 + 8 + 2 * 128 + 4 * 16 * 128 + 4 * 16 * 136 + 2 * 16 * 136) * 4;

// ================= agg v1 (layer 2: D=64, JT=256), pre-cvt p, f32 output =================
template <int D, int JT, bool RELU>
__global__ __launch_bounds__(256) void agg_tc(
    const float* __restrict__ adj,
    const float* __restrict__ feat,
    const float* __restrict__ el,
    const float* __restrict__ er,
    const float* __restrict__ bias,
    float* __restrict__ out) {
    constexpr int PP = JT + 8;
    constexpr int FP = D + 8;
    constexpr int WJ = JT / 64;
    constexpr int NSUB = 256 / JT;
    constexpr int ADJ_ST = 16 * JT;
    constexpr int F_ST   = 16 * FP;
    constexpr int P_ST   = 16 * PP;

    extern __shared__ float sm[];
    float* el_s  = sm;
    float* er_s  = el_s + NN;
    float* m_s   = er_s + JT;
    float* sc_s  = m_s + JT;
    float* red   = sc_s + JT;
    float* s_red = red + 8;
    float* adj_s = s_red + NSUB * JT;
    float* f_s   = adj_s + 3 * ADJ_ST;
    float* p_s   = f_s + 3 * F_ST;

    int bc = blockIdx.z, h = blockIdx.y;
    int c = bc % C;
    int j0 = blockIdx.x * JT;
    int tid = threadIdx.x;
    int lane = tid & 31, warp = tid >> 5;
    int jm = warp % WJ, dn = warp / WJ;
    int gr = lane >> 2, tg = lane & 3;

    const float* adj_bc = adj + (size_t)bc * NN * NN;
    const float* elh = el + (size_t)(bc * H + h) * NN;
    const float* erh = er + (size_t)(bc * H + h) * NN;
    const float* featb = feat + (size_t)bc * NN * (H * D) + h * D;

    uint32_t smem_u32 = (uint32_t)__cvta_generic_to_shared(sm);
    uint32_t adj_u32  = smem_u32 + (uint32_t)((adj_s - sm) * 4);
    uint32_t f_u32    = smem_u32 + (uint32_t)((f_s - sm) * 4);

    auto issue_stage = [&](int st, int t) {
        uint32_t aB = adj_u32 + st * ADJ_ST * 4;
#pragma unroll
        for (int l = 0; l < (16 * JT / 4) / 256; l++) {
            int s = tid + l * 256;
            int r = s / (JT / 4), cq = s % (JT / 4);
            cp16(aB + (r * JT + cq * 4) * 4,
                 adj_bc + (size_t)(t * 16 + r) * NN + j0 + cq * 4);
        }
        uint32_t fB = f_u32 + st * F_ST * 4;
#pragma unroll
        for (int l = 0; l < (16 * D / 4) / 256; l++) {
            int s = tid + l * 256;
            int r = s / (D / 4), cq = s % (D / 4);
            cp16(fB + (r * FP + cq * 4) * 4,
                 featb + (size_t)(t * 16 + r) * (H * D) + cq * 4);
        }
    };

    float e0 = elh[tid], e1 = elh[tid + 256];
    el_s[tid] = e0; el_s[tid + 256] = e1;
#pragma unroll
    for (int t = tid; t < JT; t += 256) er_s[t] = erh[j0 + t];

    issue_stage(0, 0);
    asm volatile("cp.async.commit_group;\n" ::);
    issue_stage(1, 1);
    asm volatile("cp.async.commit_group;\n" ::);

    float v = fmaxf(e0, e1);
#pragma unroll
    for (int o = 16; o; o >>= 1) v = fmaxf(v, __shfl_xor_sync(0xffffffffu, v, o));
    if (lane == 0) red[warp] = v;
    __syncthreads();
    if (tid == 0) {
        float m = red[0];
#pragma unroll
        for (int w = 1; w < 8; w++) m = fmaxf(m, red[w]);
        red[0] = m;
    }
    __syncthreads();
#pragma unroll
    for (int t = tid; t < JT; t += 256) {
        float e = red[0] + er_s[t];
        m_s[t] = e > 0.f ? e : 0.2f * e;
    }

    int pj  = tid % JT;
    int pi0 = tid / JT;

    float acc[4][4][4] = {};
    float s_priv = 0.f;

    constexpr int T = NN / 16;
    for (int i = 0; i < T; i++) {
        asm volatile("cp.async.wait_group 1;\n" ::);
        __syncthreads();

        const float* a_st = adj_s + (i % 3) * ADJ_ST;
        float* p_buf = p_s + (i & 1) * P_ST;
#pragma unroll
        for (int q = 0; q < 16 / NSUB; q++) {
            int r = pi0 + q * NSUB;
            float a = a_st[r * JT + pj];
            float pt = 0.f;
            if (a > 0.f) {
                float e = el_s[i * 16 + r] + er_s[pj];
                e = e > 0.f ? e : 0.2f * e;
                float p = __expf(e - m_s[pj]);
                pt = __uint_as_float(f2tf32(p));
                s_priv += pt;
            }
            p_buf[r * PP + pj] = pt;
        }
        __syncthreads();

        const float* f_st = f_s + (i % 3) * F_ST;
#pragma unroll
        for (int ks = 0; ks < 16; ks += 8) {
            int kA = ks + tg;
            uint32_t ah[4][4];
#pragma unroll
            for (int mt = 0; mt < 4; mt++) {
                int jb = jm * 64 + mt * 16 + gr;
                ah[mt][0] = ldu32(p_buf + kA * PP + jb);
                ah[mt][1] = ldu32(p_buf + kA * PP + jb + 8);
                ah[mt][2] = ldu32(p_buf + (kA + 4) * PP + jb);
                ah[mt][3] = ldu32(p_buf + (kA + 4) * PP + jb + 8);
            }
#pragma unroll
            for (int nt = 0; nt < 4; nt++) {
                int db = dn * 32 + nt * 8 + gr;
                float w0 = f_st[kA * FP + db];
                float w1 = f_st[(kA + 4) * FP + db];
                uint32_t bh[2], bl[2];
                bh[0] = f2tf32(w0); bl[0] = f2tf32(w0 - __uint_as_float(bh[0]));
                bh[1] = f2tf32(w1); bl[1] = f2tf32(w1 - __uint_as_float(bh[1]));
#pragma unroll
                for (int mt = 0; mt < 4; mt++) {
                    mma_tf32(acc[mt][nt], ah[mt], bh);
                    mma_tf32(acc[mt][nt], ah[mt], bl);
                }
            }
        }

        if (i + 2 < T) issue_stage((i + 2) % 3, i + 2);
        asm volatile("cp.async.commit_group;\n" ::);
    }

    s_red[pi0 * JT + pj] = s_priv;
    __syncthreads();
#pragma unroll
    for (int t = tid; t < JT; t += 256) {
        float sv = s_red[t];
        if (NSUB == 2) sv += s_red[JT + t];
        sc_s[t] = 1.0f / fmaxf(sv, 1e-9f);
    }
    __syncthreads();

    const float* bh_ = bias + (size_t)c * (H * D) + h * D;
#pragma unroll
    for (int mt = 0; mt < 4; mt++) {
#pragma unroll
        for (int nt = 0; nt < 4; nt++) {
            int jl = jm * 64 + mt * 16 + gr;
            int d  = dn * 32 + nt * 8 + tg * 2;
            float bb0 = bh_[d], bb1 = bh_[d + 1];
            float sc0 = sc_s[jl], sc1 = sc_s[jl + 8];
            float o0 = acc[mt][nt][0] * sc0 + bb0;
            float o1 = acc[mt][nt][1] * sc0 + bb1;
            float o2 = acc[mt][nt][2] * sc1 + bb0;
            float o3 = acc[mt][nt][3] * sc1 + bb1;
            if (RELU) {
                o0 = fmaxf(o0, 0.f); o1 = fmaxf(o1, 0.f);
                o2 = fmaxf(o2, 0.f); o3 = fmaxf(o3, 0.f);
            }
            int j = j0 + jl;
            *(float2*)(out + ((size_t)bc * NN + j) * (H * D) + h * D + d)     = make_float2(o0, o1);
            *(float2*)(out + ((size_t)bc * NN + j + 8) * (H * D) + h * D + d) = make_float2(o2, o3);
        }
    }
}

constexpr int agg_smem_bytes(int D, int JT) {
    int FP = D + 8, PP = JT + 8, NSUB = 256 / JT;
    return (NN + 3 * JT + 8 + NSUB * JT + 3 * 16 * JT + 3 * 16 * FP + 2 * 16 * PP) * 4;
}
constexpr int AGG_SMEM_64 = agg_smem_bytes(64, 256);

// ---------------- head-mean + channel concat ----------------
__global__ void mean_kernel(const float* __restrict__ in2, float* __restrict__ out) {
    int idx = blockIdx.x * 256 + threadIdx.x;
    if (idx >= B * NN * C * DOUT) return;
    int d = idx % DOUT;
    int c = (idx / DOUT) % C;
    int n = (idx / (DOUT * C)) % NN;
    int b = idx / (DOUT * C * NN);
    const float* p = in2 + ((size_t)(b * C + c) * NN + n) * HD2 + d;
    out[idx] = 0.25f * (p[0] + p[DOUT] + p[2 * DOUT] + p[3 * DOUT]);
}

// ---------------- launch ----------------
extern "C" void kernel_launch(void* const* d_in, const int* in_sizes, int n_in,
                              void* d_out, int out_size) {
    const float* x   = (const float*)d_in[0];
    const float* adj = (const float*)d_in[1];
    const float* W0  = (const float*)d_in[2];
    const float* al0 = (const float*)d_in[3];
    const float* ar0 = (const float*)d_in[4];
    const float* b0  = (const float*)d_in[5];
    const float* W1  = (const float*)d_in[6];
    const float* al1 = (const float*)d_in[7];
    const float* ar1 = (const float*)d_in[8];
    const float* b1  = (const float*)d_in[9];
    const float* W2  = (const float*)d_in[10];
    const float* al2 = (const float*)d_in[11];
    const float* ar2 = (const float*)d_in[12];
    const float* b2  = (const float*)d_in[13];
    float* out = (float*)d_out;

    float *feat, *hhi, *hlo, *xhi, *xlo, *el, *er, *out2;
    cudaGetSymbolAddress((void**)&feat, g_feat);
    cudaGetSymbolAddress((void**)&hhi,  g_hhi);
    cudaGetSymbolAddress((void**)&hlo,  g_hlo);
    cudaGetSymbolAddress((void**)&xhi,  g_xhi);
    cudaGetSymbolAddress((void**)&xlo,  g_xlo);
    cudaGetSymbolAddress((void**)&el,   g_el);
    cudaGetSymbolAddress((void**)&er,   g_er);
    cudaGetSymbolAddress((void**)&out2, g_out2);

    dim3 t256(256);
    static int attr_set = 0;
    if (!attr_set) {
        cudaFuncSetAttribute(gemm_tc, cudaFuncAttributeMaxDynamicSharedMemorySize, GEMM_SMEM);
        cudaFuncSetAttribute(agg_tc2<true>,
                             cudaFuncAttributeMaxDynamicSharedMemorySize, AGG2_SMEM);
        cudaFuncSetAttribute(agg_tc<DOUT, 256, false>,
                             cudaFuncAttributeMaxDynamicSharedMemorySize, AGG_SMEM_64);
        attr_set = 1;
    }

    size_t elr_bytes = (size_t)BC * H * NN * sizeof(float);

    // ---- prep: pre-split x[:,0] ----
    split_x<<<(B * NN * FIN + 255) / 256, t256>>>(x, xhi, xlo);

    // ---- layer 0 ----
    cudaMemsetAsync(el, 0, elr_bytes);
    cudaMemsetAsync(er, 0, elr_bytes);
    gemm_tc<<<dim3(HD / 128, NN / 128, BC), t256, GEMM_SMEM>>>(
        xhi, xlo, W0, feat, FIN, HD, (size_t)NN * FIN, 0, al0, ar0, el, er, DHID);
    agg_tc2<true><<<dim3(NN / 128, H, BC), t256, AGG2_SMEM>>>(adj, feat, el, er, b0, hhi, hlo);

    // ---- layer 1 ----
    cudaMemsetAsync(el, 0, elr_bytes);
    cudaMemsetAsync(er, 0, elr_bytes);
    gemm_tc<<<dim3(HD / 128, NN / 128, BC), t256, GEMM_SMEM>>>(
        hhi, hlo, W1, feat, HD, HD, (size_t)C * NN * HD, (size_t)NN * HD, al1, ar1, el, er, DHID);
    agg_tc2<true><<<dim3(NN / 128, H, BC), t256, AGG2_SMEM>>>(adj, feat, el, er, b1, hhi, hlo);

    // ---- layer 2 ----
    cudaMemsetAsync(el, 0, elr_bytes);
    cudaMemsetAsync(er, 0, elr_bytes);
    gemm_tc<<<dim3(HD2 / 128, NN / 128, BC), t256, GEMM_SMEM>>>(
        hhi, hlo, W2, feat, HD, HD2, (size_t)C * NN * HD, (size_t)NN * HD, al2, ar2, el, er, DOUT);
    agg_tc<DOUT, 256, false><<<dim3(NN / 256, H, BC), t256, AGG_SMEM_64>>>(adj, feat, el, er, b2, out2);

    // ---- head mean + concat ----
    mean_kernel<<<(B * NN * C * DOUT + 255) / 256, t256>>>(out2, out);
}

// round 11
// speedup vs baseline: 1.0420x; 1.0420x over previous
#include <cuda_runtime.h>
#include <cstdint>

// ---------------- problem constants ----------------
constexpr int B    = 8;
constexpr int C    = 5;
constexpr int NN   = 512;
constexpr int FIN  = 768;
constexpr int H    = 4;
constexpr int DHID = 128;
constexpr int DOUT = 64;
constexpr int HD   = H * DHID;   // 512
constexpr int HD2  = H * DOUT;   // 256
constexpr int BC   = B * C;      // 40

// ---------------- scratch ----------------
__device__ __align__(256) float g_feat[(size_t)BC * NN * HD];
__device__ __align__(256) float g_h   [(size_t)BC * NN * HD];
__device__ __align__(256) float g_out2[(size_t)BC * NN * HD2];
__device__ __align__(256) float g_elr [2 * BC * H * NN];   // [el | er]

// ---------------- gemm smem geometry ----------------
constexpr int AP = 20;
constexpr int BP = 136;
constexpr int A_STG = 128 * AP;
constexpr int B_STG = 16 * BP;
constexpr int STG   = A_STG + B_STG;
constexpr int GEMM_SMEM = 3 * STG * 4;

__device__ __forceinline__ uint32_t f2tf32(float f) {
    uint32_t u;
    asm("cvt.rna.tf32.f32 %0, %1;" : "=r"(u) : "f"(f));
    return u;
}

__device__ __forceinline__ void mma_tf32(float* d, const uint32_t* a, const uint32_t* b) {
    asm volatile(
        "mma.sync.aligned.m16n8k8.row.col.f32.tf32.tf32.f32 "
        "{%0,%1,%2,%3}, {%4,%5,%6,%7}, {%8,%9}, {%0,%1,%2,%3};\n"
        : "+f"(d[0]), "+f"(d[1]), "+f"(d[2]), "+f"(d[3])
        : "r"(a[0]), "r"(a[1]), "r"(a[2]), "r"(a[3]), "r"(b[0]), "r"(b[1]));
}

__device__ __forceinline__ void cp16(uint32_t smem_dst, const float* gsrc) {
    asm volatile("cp.async.ca.shared.global [%0], [%1], 16;\n"
                 :: "r"(smem_dst), "l"(gsrc));
}

__device__ __forceinline__ uint32_t ldu32(const float* p) {
    return __float_as_uint(*p);
}

// ---------------- tf32 GEMM (R5/R9-validated): split-at-load + fused el/er ----------
__global__ __launch_bounds__(256, 2) void gemm_tc(
    const float* __restrict__ A, const float* __restrict__ W,
    float* __restrict__ Co, int K, int Nn, size_t aSB, size_t aSC,
    const float* __restrict__ al, const float* __restrict__ ar,
    float* __restrict__ elo, float* __restrict__ ero, int Dh) {
    extern __shared__ float sm[];

    int bc = blockIdx.z;
    int b  = bc / C, c = bc % C;
    const float* Ab = A + (size_t)b * aSB + (size_t)c * aSC;
    const float* Wc = W + (size_t)c * K * Nn;
    float*       Cb = Co + (size_t)bc * NN * Nn;

    int m0 = blockIdx.y * 128, n0 = blockIdx.x * 128;
    int tid  = threadIdx.x;
    int lane = tid & 31, warp = tid >> 5;
    int wm = warp & 1, wn = warp >> 1;
    int gr = lane >> 2, tg = lane & 3;

    uint32_t smem_base = (uint32_t)__cvta_generic_to_shared(sm);

    int am0 = tid >> 2,          akq = (tid & 3) * 4;
    int am1 = (tid + 256) >> 2;
    int bk0 = tid >> 5,          bnq = (tid & 31) * 4;
    int bk1 = (tid + 256) >> 5;

    auto issue_stage = [&](int st, int t) {
        uint32_t aB = smem_base + (st * STG) * 4;
        uint32_t bB = smem_base + (st * STG + A_STG) * 4;
        const float* Abt = Ab + (size_t)m0 * K + t * 16;
        cp16(aB + (am0 * AP + akq) * 4, Abt + (size_t)am0 * K + akq);
        cp16(aB + (am1 * AP + akq) * 4, Abt + (size_t)am1 * K + akq);
        const float* Wct = Wc + (size_t)(t * 16) * Nn + n0;
        cp16(bB + (bk0 * BP + bnq) * 4, Wct + (size_t)bk0 * Nn + bnq);
        cp16(bB + (bk1 * BP + bnq) * 4, Wct + (size_t)bk1 * Nn + bnq);
    };

    float acc[4][4][4] = {};

    auto compute_stage = [&](int st) {
        const float* As = sm + st * STG;
        const float* Bs = As + A_STG;
#pragma unroll
        for (int ks = 0; ks < 16; ks += 8) {
            int kA = ks + tg;
            uint32_t ah[4][4], al_[4][4], bh[4][2], bl[4][2];
#pragma unroll
            for (int mt = 0; mt < 4; mt++) {
                int m = wm * 64 + mt * 16 + gr;
                float v0 = As[m * AP + kA];
                float v1 = As[(m + 8) * AP + kA];
                float v2 = As[m * AP + kA + 4];
                float v3 = As[(m + 8) * AP + kA + 4];
                ah[mt][0] = f2tf32(v0); al_[mt][0] = f2tf32(v0 - __uint_as_float(ah[mt][0]));
                ah[mt][1] = f2tf32(v1); al_[mt][1] = f2tf32(v1 - __uint_as_float(ah[mt][1]));
                ah[mt][2] = f2tf32(v2); al_[mt][2] = f2tf32(v2 - __uint_as_float(ah[mt][2]));
                ah[mt][3] = f2tf32(v3); al_[mt][3] = f2tf32(v3 - __uint_as_float(ah[mt][3]));
            }
#pragma unroll
            for (int nt = 0; nt < 4; nt++) {
                int n = wn * 32 + nt * 8 + gr;
                float w0 = Bs[kA * BP + n];
                float w1 = Bs[(kA + 4) * BP + n];
                bh[nt][0] = f2tf32(w0); bl[nt][0] = f2tf32(w0 - __uint_as_float(bh[nt][0]));
                bh[nt][1] = f2tf32(w1); bl[nt][1] = f2tf32(w1 - __uint_as_float(bh[nt][1]));
            }
#pragma unroll
            for (int mt = 0; mt < 4; mt++)
#pragma unroll
                for (int nt = 0; nt < 4; nt++) {
                    mma_tf32(acc[mt][nt], ah[mt], bh[nt]);
                    mma_tf32(acc[mt][nt], al_[mt], bh[nt]);
                    mma_tf32(acc[mt][nt], ah[mt], bl[nt]);
                }
        }
    };

    int T = K / 16;
    issue_stage(0, 0);
    asm volatile("cp.async.commit_group;\n" ::);
    issue_stage(1, 1);
    asm volatile("cp.async.commit_group;\n" ::);

    for (int i = 0; i < T; i++) {
        asm volatile("cp.async.wait_group 1;\n" ::);
        __syncthreads();
        if (i + 2 < T) issue_stage((i + 2) % 3, i + 2);
        asm volatile("cp.async.commit_group;\n" ::);
        compute_stage(i % 3);
    }

    // ---- epilogue: store C + fused el/er partials ----
    int head  = (n0 + wn * 32) / Dh;
    int dbase = n0 + wn * 32 - head * Dh;
    const float* alh = al + ((size_t)c * H + head) * Dh;
    const float* arh = ar + ((size_t)c * H + head) * Dh;
    float* elh = elo + ((size_t)bc * H + head) * NN;
    float* erh = ero + ((size_t)bc * H + head) * NN;

#pragma unroll
    for (int mt = 0; mt < 4; mt++) {
        float el0 = 0.f, el1 = 0.f, er0 = 0.f, er1 = 0.f;
#pragma unroll
        for (int nt = 0; nt < 4; nt++) {
            int row = m0 + wm * 64 + mt * 16 + gr;
            int col = n0 + wn * 32 + nt * 8 + tg * 2;
            *(float2*)(Cb + (size_t)row * Nn + col) =
                make_float2(acc[mt][nt][0], acc[mt][nt][1]);
            *(float2*)(Cb + (size_t)(row + 8) * Nn + col) =
                make_float2(acc[mt][nt][2], acc[mt][nt][3]);

            int d = dbase + nt * 8 + tg * 2;
            float a0 = alh[d], a1 = alh[d + 1];
            float r0 = arh[d], r1 = arh[d + 1];
            el0 += acc[mt][nt][0] * a0 + acc[mt][nt][1] * a1;
            el1 += acc[mt][nt][2] * a0 + acc[mt][nt][3] * a1;
            er0 += acc[mt][nt][0] * r0 + acc[mt][nt][1] * r1;
            er1 += acc[mt][nt][2] * r0 + acc[mt][nt][3] * r1;
        }
#pragma unroll
        for (int o = 1; o < 4; o <<= 1) {
            el0 += __shfl_xor_sync(0xffffffffu, el0, o);
            el1 += __shfl_xor_sync(0xffffffffu, el1, o);
            er0 += __shfl_xor_sync(0xffffffffu, er0, o);
            er1 += __shfl_xor_sync(0xffffffffu, er1, o);
        }
        if (tg == 0) {
            int row = m0 + wm * 64 + mt * 16 + gr;
            atomicAdd(elh + row,     el0);
            atomicAdd(elh + row + 8, el1);
            atomicAdd(erh + row,     er0);
            atomicAdd(erh + row + 8, er1);
        }
    }
}

// ================= agg v2 (D=128, JT=128): produce-ahead, pre-cvt p =================
template <bool RELU>
__global__ __launch_bounds__(256, 2) void agg_tc2(
    const float* __restrict__ adj,
    const float* __restrict__ feat,
    const float* __restrict__ el,
    const float* __restrict__ er,
    const float* __restrict__ bias,
    float* __restrict__ out) {
    constexpr int D  = 128, JT = 128;
    constexpr int PP = JT + 8;
    constexpr int FP = D + 8;
    constexpr int NSUB = 256 / JT;
    constexpr int ADJ_ST = 16 * JT;
    constexpr int F_ST   = 16 * FP;
    constexpr int P_ST   = 16 * PP;
    constexpr int T = NN / 16;

    extern __shared__ float sm[];
    float* el_s  = sm;
    float* er_s  = el_s + NN;
    float* m_s   = er_s + JT;
    float* sc_s  = m_s + JT;
    float* red   = sc_s + JT;
    float* s_red = red + 8;
    float* adj_s = s_red + NSUB * JT;
    float* f_s   = adj_s + 4 * ADJ_ST;
    float* p_s   = f_s + 4 * F_ST;

    int bc = blockIdx.z, h = blockIdx.y;
    int c = bc % C;
    int j0 = blockIdx.x * JT;
    int tid = threadIdx.x;
    int lane = tid & 31, warp = tid >> 5;
    int jm = warp & 1, dn = warp >> 1;
    int gr = lane >> 2, tg = lane & 3;

    const float* adj_bc = adj + (size_t)bc * NN * NN;
    const float* elh = el + (size_t)(bc * H + h) * NN;
    const float* erh = er + (size_t)(bc * H + h) * NN;
    const float* featb = feat + (size_t)bc * NN * (H * D) + h * D;

    uint32_t smem_u32 = (uint32_t)__cvta_generic_to_shared(sm);
    uint32_t adj_u32  = smem_u32 + (uint32_t)((adj_s - sm) * 4);
    uint32_t f_u32    = smem_u32 + (uint32_t)((f_s - sm) * 4);

    auto issue_stage = [&](int st, int t) {
        uint32_t aB = adj_u32 + st * ADJ_ST * 4;
#pragma unroll
        for (int l = 0; l < (16 * JT / 4) / 256; l++) {
            int s = tid + l * 256;
            int r = s / (JT / 4), cq = s % (JT / 4);
            cp16(aB + (r * JT + cq * 4) * 4,
                 adj_bc + (size_t)(t * 16 + r) * NN + j0 + cq * 4);
        }
        uint32_t fB = f_u32 + st * F_ST * 4;
#pragma unroll
        for (int l = 0; l < (16 * D / 4) / 256; l++) {
            int s = tid + l * 256;
            int r = s / (D / 4), cq = s % (D / 4);
            cp16(fB + (r * FP + cq * 4) * 4,
                 featb + (size_t)(t * 16 + r) * (H * D) + cq * 4);
        }
    };

    float e0 = elh[tid], e1 = elh[tid + 256];
    el_s[tid] = e0; el_s[tid + 256] = e1;
    if (tid < JT) er_s[tid] = erh[j0 + tid];

    issue_stage(0, 0);
    asm volatile("cp.async.commit_group;\n" ::);
    issue_stage(1, 1);
    asm volatile("cp.async.commit_group;\n" ::);
    issue_stage(2, 2);
    asm volatile("cp.async.commit_group;\n" ::);

    float v = fmaxf(e0, e1);
#pragma unroll
    for (int o = 16; o; o >>= 1) v = fmaxf(v, __shfl_xor_sync(0xffffffffu, v, o));
    if (lane == 0) red[warp] = v;
    __syncthreads();
    if (tid == 0) {
        float m = red[0];
#pragma unroll
        for (int w = 1; w < 8; w++) m = fmaxf(m, red[w]);
        red[0] = m;
    }
    __syncthreads();
    if (tid < JT) {
        float e = red[0] + er_s[tid];
        m_s[tid] = e > 0.f ? e : 0.2f * e;
    }

    int pj  = tid % JT;
    int pi0 = tid / JT;
    float s_priv = 0.f;

    // produce p(t) pre-converted to tf32 bits (consistent numerator/denominator)
    auto produce = [&](int t) {
        const float* a_st = adj_s + (t % 4) * ADJ_ST;
        float* p_nb = p_s + (t & 1) * P_ST;
#pragma unroll
        for (int q = 0; q < 16 / NSUB; q++) {
            int r = pi0 + q * NSUB;
            float a = a_st[r * JT + pj];
            float pt = 0.f;
            if (a > 0.f) {
                float e = el_s[t * 16 + r] + er_s[pj];
                e = e > 0.f ? e : 0.2f * e;
                float p = __expf(e - m_s[pj]);
                pt = __uint_as_float(f2tf32(p));
                s_priv += pt;
            }
            p_nb[r * PP + pj] = pt;
        }
    };

    asm volatile("cp.async.wait_group 2;\n" ::);
    __syncthreads();
    produce(0);

    float acc[4][4][4] = {};

    for (int i = 0; i < T; i++) {
        asm volatile("cp.async.wait_group 1;\n" ::);
        __syncthreads();

        const float* f_st  = f_s + (i % 4) * F_ST;
        const float* p_buf = p_s + (i & 1) * P_ST;
#pragma unroll
        for (int ks = 0; ks < 16; ks += 8) {
            int kA = ks + tg;
            uint32_t ah[4][4];
#pragma unroll
            for (int mt = 0; mt < 4; mt++) {
                int jb = jm * 64 + mt * 16 + gr;
                ah[mt][0] = ldu32(p_buf + kA * PP + jb);
                ah[mt][1] = ldu32(p_buf + kA * PP + jb + 8);
                ah[mt][2] = ldu32(p_buf + (kA + 4) * PP + jb);
                ah[mt][3] = ldu32(p_buf + (kA + 4) * PP + jb + 8);
            }
#pragma unroll
            for (int nt = 0; nt < 4; nt++) {
                int db = dn * 32 + nt * 8 + gr;
                float w0 = f_st[kA * FP + db];
                float w1 = f_st[(kA + 4) * FP + db];
                uint32_t bh[2], bl[2];
                bh[0] = f2tf32(w0); bl[0] = f2tf32(w0 - __uint_as_float(bh[0]));
                bh[1] = f2tf32(w1); bl[1] = f2tf32(w1 - __uint_as_float(bh[1]));
#pragma unroll
                for (int mt = 0; mt < 4; mt++) {
                    mma_tf32(acc[mt][nt], ah[mt], bh);
                    mma_tf32(acc[mt][nt], ah[mt], bl);
                }
            }
        }

        if (i + 1 < T) produce(i + 1);

        if (i + 3 < T) issue_stage((i + 3) % 4, i + 3);
        asm volatile("cp.async.commit_group;\n" ::);
    }

    s_red[pi0 * JT + pj] = s_priv;
    __syncthreads();
    if (tid < JT)
        sc_s[tid] = 1.0f / fmaxf(s_red[tid] + s_red[JT + tid], 1e-9f);
    __syncthreads();

    const float* bh_ = bias + (size_t)c * (H * D) + h * D;
#pragma unroll
    for (int mt = 0; mt < 4; mt++) {
#pragma unroll
        for (int nt = 0; nt < 4; nt++) {
            int jl = jm * 64 + mt * 16 + gr;
            int d  = dn * 32 + nt * 8 + tg * 2;
            float bb0 = bh_[d], bb1 = bh_[d + 1];
            float sc0 = sc_s[jl], sc1 = sc_s[jl + 8];
            float o0 = acc[mt][nt][0] * sc0 + bb0;
            float o1 = acc[mt][nt][1] * sc0 + bb1;
            float o2 = acc[mt][nt][2] * sc1 + bb0;
            float o3 = acc[mt][nt][3] * sc1 + bb1;
            if (RELU) {
                o0 = fmaxf(o0, 0.f); o1 = fmaxf(o1, 0.f);
                o2 = fmaxf(o2, 0.f); o3 = fmaxf(o3, 0.f);
            }
            int j = j0 + jl;
            *(float2*)(out + ((size_t)bc * NN + j) * (H * D) + h * D + d)     = make_float2(o0, o1);
            *(float2*)(out + ((size_t)bc * NN + j + 8) * (H * D) + h * D + d) = make_float2(o2, o3);
        }
    }
}

constexpr int AGG2_SMEM = (NN + 3 * 128 + 8 + 2 * 128 + 4 * 16 * 128 + 4 * 16 * 136 + 2 * 16 * 136) * 4;

// ================= agg v1 (layer 2: D=64, JT=256), pre-cvt p =================
template <int D, int JT, bool RELU>
__global__ __launch_bounds__(256) void agg_tc(
    const float* __restrict__ adj,
    const float* __restrict__ feat,
    const float* __restrict__ el,
    const float* __restrict__ er,
    const float* __restrict__ bias,
    float* __restrict__ out) {
    constexpr int PP = JT + 8;
    constexpr int FP = D + 8;
    constexpr int WJ = JT / 64;
    constexpr int NSUB = 256 / JT;
    constexpr int ADJ_ST = 16 * JT;
    constexpr int F_ST   = 16 * FP;
    constexpr int P_ST   = 16 * PP;

    extern __shared__ float sm[];
    float* el_s  = sm;
    float* er_s  = el_s + NN;
    float* m_s   = er_s + JT;
    float* sc_s  = m_s + JT;
    float* red   = sc_s + JT;
    float* s_red = red + 8;
    float* adj_s = s_red + NSUB * JT;
    float* f_s   = adj_s + 3 * ADJ_ST;
    float* p_s   = f_s + 3 * F_ST;

    int bc = blockIdx.z, h = blockIdx.y;
    int c = bc % C;
    int j0 = blockIdx.x * JT;
    int tid = threadIdx.x;
    int lane = tid & 31, warp = tid >> 5;
    int jm = warp % WJ, dn = warp / WJ;
    int gr = lane >> 2, tg = lane & 3;

    const float* adj_bc = adj + (size_t)bc * NN * NN;
    const float* elh = el + (size_t)(bc * H + h) * NN;
    const float* erh = er + (size_t)(bc * H + h) * NN;
    const float* featb = feat + (size_t)bc * NN * (H * D) + h * D;

    uint32_t smem_u32 = (uint32_t)__cvta_generic_to_shared(sm);
    uint32_t adj_u32  = smem_u32 + (uint32_t)((adj_s - sm) * 4);
    uint32_t f_u32    = smem_u32 + (uint32_t)((f_s - sm) * 4);

    auto issue_stage = [&](int st, int t) {
        uint32_t aB = adj_u32 + st * ADJ_ST * 4;
#pragma unroll
        for (int l = 0; l < (16 * JT / 4) / 256; l++) {
            int s = tid + l * 256;
            int r = s / (JT / 4), cq = s % (JT / 4);
            cp16(aB + (r * JT + cq * 4) * 4,
                 adj_bc + (size_t)(t * 16 + r) * NN + j0 + cq * 4);
        }
        uint32_t fB = f_u32 + st * F_ST * 4;
#pragma unroll
        for (int l = 0; l < (16 * D / 4) / 256; l++) {
            int s = tid + l * 256;
            int r = s / (D / 4), cq = s % (D / 4);
            cp16(fB + (r * FP + cq * 4) * 4,
                 featb + (size_t)(t * 16 + r) * (H * D) + cq * 4);
        }
    };

    float e0 = elh[tid], e1 = elh[tid + 256];
    el_s[tid] = e0; el_s[tid + 256] = e1;
#pragma unroll
    for (int t = tid; t < JT; t += 256) er_s[t] = erh[j0 + t];

    issue_stage(0, 0);
    asm volatile("cp.async.commit_group;\n" ::);
    issue_stage(1, 1);
    asm volatile("cp.async.commit_group;\n" ::);

    float v = fmaxf(e0, e1);
#pragma unroll
    for (int o = 16; o; o >>= 1) v = fmaxf(v, __shfl_xor_sync(0xffffffffu, v, o));
    if (lane == 0) red[warp] = v;
    __syncthreads();
    if (tid == 0) {
        float m = red[0];
#pragma unroll
        for (int w = 1; w < 8; w++) m = fmaxf(m, red[w]);
        red[0] = m;
    }
    __syncthreads();
#pragma unroll
    for (int t = tid; t < JT; t += 256) {
        float e = red[0] + er_s[t];
        m_s[t] = e > 0.f ? e : 0.2f * e;
    }

    int pj  = tid % JT;
    int pi0 = tid / JT;

    float acc[4][4][4] = {};
    float s_priv = 0.f;

    constexpr int T = NN / 16;
    for (int i = 0; i < T; i++) {
        asm volatile("cp.async.wait_group 1;\n" ::);
        __syncthreads();

        const float* a_st = adj_s + (i % 3) * ADJ_ST;
        float* p_buf = p_s + (i & 1) * P_ST;
#pragma unroll
        for (int q = 0; q < 16 / NSUB; q++) {
            int r = pi0 + q * NSUB;
            float a = a_st[r * JT + pj];
            float pt = 0.f;
            if (a > 0.f) {
                float e = el_s[i * 16 + r] + er_s[pj];
                e = e > 0.f ? e : 0.2f * e;
                float p = __expf(e - m_s[pj]);
                pt = __uint_as_float(f2tf32(p));
                s_priv += pt;
            }
            p_buf[r * PP + pj] = pt;
        }
        __syncthreads();

        const float* f_st = f_s + (i % 3) * F_ST;
#pragma unroll
        for (int ks = 0; ks < 16; ks += 8) {
            int kA = ks + tg;
            uint32_t ah[4][4];
#pragma unroll
            for (int mt = 0; mt < 4; mt++) {
                int jb = jm * 64 + mt * 16 + gr;
                ah[mt][0] = ldu32(p_buf + kA * PP + jb);
                ah[mt][1] = ldu32(p_buf + kA * PP + jb + 8);
                ah[mt][2] = ldu32(p_buf + (kA + 4) * PP + jb);
                ah[mt][3] = ldu32(p_buf + (kA + 4) * PP + jb + 8);
            }
#pragma unroll
            for (int nt = 0; nt < 4; nt++) {
                int db = dn * 32 + nt * 8 + gr;
                float w0 = f_st[kA * FP + db];
                float w1 = f_st[(kA + 4) * FP + db];
                uint32_t bh[2], bl[2];
                bh[0] = f2tf32(w0); bl[0] = f2tf32(w0 - __uint_as_float(bh[0]));
                bh[1] = f2tf32(w1); bl[1] = f2tf32(w1 - __uint_as_float(bh[1]));
#pragma unroll
                for (int mt = 0; mt < 4; mt++) {
                    mma_tf32(acc[mt][nt], ah[mt], bh);
                    mma_tf32(acc[mt][nt], ah[mt], bl);
                }
            }
        }

        if (i + 2 < T) issue_stage((i + 2) % 3, i + 2);
        asm volatile("cp.async.commit_group;\n" ::);
    }

    s_red[pi0 * JT + pj] = s_priv;
    __syncthreads();
#pragma unroll
    for (int t = tid; t < JT; t += 256) {
        float sv = s_red[t];
        if (NSUB == 2) sv += s_red[JT + t];
        sc_s[t] = 1.0f / fmaxf(sv, 1e-9f);
    }
    __syncthreads();

    const float* bh_ = bias + (size_t)c * (H * D) + h * D;
#pragma unroll
    for (int mt = 0; mt < 4; mt++) {
#pragma unroll
        for (int nt = 0; nt < 4; nt++) {
            int jl = jm * 64 + mt * 16 + gr;
            int d  = dn * 32 + nt * 8 + tg * 2;
            float bb0 = bh_[d], bb1 = bh_[d + 1];
            float sc0 = sc_s[jl], sc1 = sc_s[jl + 8];
            float o0 = acc[mt][nt][0] * sc0 + bb0;
            float o1 = acc[mt][nt][1] * sc0 + bb1;
            float o2 = acc[mt][nt][2] * sc1 + bb0;
            float o3 = acc[mt][nt][3] * sc1 + bb1;
            if (RELU) {
                o0 = fmaxf(o0, 0.f); o1 = fmaxf(o1, 0.f);
                o2 = fmaxf(o2, 0.f); o3 = fmaxf(o3, 0.f);
            }
            int j = j0 + jl;
            *(float2*)(out + ((size_t)bc * NN + j) * (H * D) + h * D + d)     = make_float2(o0, o1);
            *(float2*)(out + ((size_t)bc * NN + j + 8) * (H * D) + h * D + d) = make_float2(o2, o3);
        }
    }
}

constexpr int agg_smem_bytes(int D, int JT) {
    int FP = D + 8, PP = JT + 8, NSUB = 256 / JT;
    return (NN + 3 * JT + 8 + NSUB * JT + 3 * 16 * JT + 3 * 16 * FP + 2 * 16 * PP) * 4;
}
constexpr int AGG_SMEM_64 = agg_smem_bytes(64, 256);

// ---------------- head-mean + channel concat ----------------
__global__ void mean_kernel(const float* __restrict__ in2, float* __restrict__ out) {
    int idx = blockIdx.x * 256 + threadIdx.x;
    if (idx >= B * NN * C * DOUT) return;
    int d = idx % DOUT;
    int c = (idx / DOUT) % C;
    int n = (idx / (DOUT * C)) % NN;
    int b = idx / (DOUT * C * NN);
    const float* p = in2 + ((size_t)(b * C + c) * NN + n) * HD2 + d;
    out[idx] = 0.25f * (p[0] + p[DOUT] + p[2 * DOUT] + p[3 * DOUT]);
}

// ---------------- launch ----------------
extern "C" void kernel_launch(void* const* d_in, const int* in_sizes, int n_in,
                              void* d_out, int out_size) {
    const float* x   = (const float*)d_in[0];
    const float* adj = (const float*)d_in[1];
    const float* W0  = (const float*)d_in[2];
    const float* al0 = (const float*)d_in[3];
    const float* ar0 = (const float*)d_in[4];
    const float* b0  = (const float*)d_in[5];
    const float* W1  = (const float*)d_in[6];
    const float* al1 = (const float*)d_in[7];
    const float* ar1 = (const float*)d_in[8];
    const float* b1  = (const float*)d_in[9];
    const float* W2  = (const float*)d_in[10];
    const float* al2 = (const float*)d_in[11];
    const float* ar2 = (const float*)d_in[12];
    const float* b2  = (const float*)d_in[13];
    float* out = (float*)d_out;

    float *feat, *hbuf, *elr, *out2;
    cudaGetSymbolAddress((void**)&feat, g_feat);
    cudaGetSymbolAddress((void**)&hbuf, g_h);
    cudaGetSymbolAddress((void**)&elr,  g_elr);
    cudaGetSymbolAddress((void**)&out2, g_out2);
    float* el = elr;
    float* er = elr + BC * H * NN;

    dim3 t256(256);
    static int attr_set = 0;
    if (!attr_set) {
        cudaFuncSetAttribute(gemm_tc, cudaFuncAttributeMaxDynamicSharedMemorySize, GEMM_SMEM);
        cudaFuncSetAttribute(agg_tc2<true>,
                             cudaFuncAttributeMaxDynamicSharedMemorySize, AGG2_SMEM);
        cudaFuncSetAttribute(agg_tc<DOUT, 256, false>,
                             cudaFuncAttributeMaxDynamicSharedMemorySize, AGG_SMEM_64);
        attr_set = 1;
    }

    size_t elr_bytes = (size_t)2 * BC * H * NN * sizeof(float);

    // ---- layer 0 ----
    cudaMemsetAsync(elr, 0, elr_bytes);
    gemm_tc<<<dim3(HD / 128, NN / 128, BC), t256, GEMM_SMEM>>>(
        x, W0, feat, FIN, HD, (size_t)C * NN * FIN, 0, al0, ar0, el, er, DHID);
    agg_tc2<true><<<dim3(NN / 128, H, BC), t256, AGG2_SMEM>>>(adj, feat, el, er, b0, hbuf);

    // ---- layer 1 ----
    cudaMemsetAsync(elr, 0, elr_bytes);
    gemm_tc<<<dim3(HD / 128, NN / 128, BC), t256, GEMM_SMEM>>>(
        hbuf, W1, feat, HD, HD, (size_t)C * NN * HD, (size_t)NN * HD, al1, ar1, el, er, DHID);
    agg_tc2<true><<<dim3(NN / 128, H, BC), t256, AGG2_SMEM>>>(adj, feat, el, er, b1, hbuf);

    // ---- layer 2 ----
    cudaMemsetAsync(elr, 0, elr_bytes);
    gemm_tc<<<dim3(HD2 / 128, NN / 128, BC), t256, GEMM_SMEM>>>(
        hbuf, W2, feat, HD, HD2, (size_t)C * NN * HD, (size_t)NN * HD, al2, ar2, el, er, DOUT);
    agg_tc<DOUT, 256, false><<<dim3(NN / 256, H, BC), t256, AGG_SMEM_64>>>(adj, feat, el, er, b2, out2);

    // ---- head mean + concat ----
    mean_kernel<<<(B * NN * C * DOUT + 255) / 256, t256>>>(out2, out);
}

// round 12
// speedup vs baseline: 1.3878x; 1.3318x over previous
#include <cuda_runtime.h>
#include <cuda_bf16.h>
#include <cstdint>

// ---------------- problem constants ----------------
constexpr int B    = 8;
constexpr int C    = 5;
constexpr int NN   = 512;
constexpr int FIN  = 768;
constexpr int H    = 4;
constexpr int DHID = 128;
constexpr int DOUT = 64;
constexpr int HD   = H * DHID;   // 512
constexpr int HD2  = H * DOUT;   // 256
constexpr int BC   = B * C;      // 40

// ---------------- scratch ----------------
__device__ __align__(256) float g_feat[(size_t)BC * NN * HD];
__device__ __align__(256) float g_h   [(size_t)BC * NN * HD];
__device__ __align__(256) float g_out2[(size_t)BC * NN * HD2];
__device__ __align__(256) float g_elr [2 * BC * H * NN];   // [el | er]

// ---------------- gemm smem geometry ----------------
constexpr int AP = 20;            // A pitch (f32 words)
constexpr int BP = 132;           // B pitch: bf16 frag loads (8tg+gr)%32 conflict-free
constexpr int A_STG = 128 * AP;   // 2560
constexpr int B_STG = 16 * BP;    // 2112
constexpr int STG   = A_STG + B_STG;
constexpr int GEMM_SMEM = 3 * STG * 4;   // 56064 B

// ---------------- bf16 helpers ----------------
__device__ __forceinline__ uint32_t packbf2(float hi, float lo) {
    uint32_t d;
    asm("cvt.rn.bf16x2.f32 %0, %1, %2;" : "=r"(d) : "f"(hi), "f"(lo));
    return d;
}
__device__ __forceinline__ float bflo(uint32_t u) { return __uint_as_float(u << 16); }
__device__ __forceinline__ float bfhi(uint32_t u) { return __uint_as_float(u & 0xffff0000u); }

__device__ __forceinline__ void mma_bf16(float* d, const uint32_t* a, const uint32_t* b) {
    asm volatile(
        "mma.sync.aligned.m16n8k16.row.col.f32.bf16.bf16.f32 "
        "{%0,%1,%2,%3}, {%4,%5,%6,%7}, {%8,%9}, {%0,%1,%2,%3};\n"
        : "+f"(d[0]), "+f"(d[1]), "+f"(d[2]), "+f"(d[3])
        : "r"(a[0]), "r"(a[1]), "r"(a[2]), "r"(a[3]), "r"(b[0]), "r"(b[1]));
}

__device__ __forceinline__ void cp16(uint32_t smem_dst, const float* gsrc) {
    asm volatile("cp.async.ca.shared.global [%0], [%1], 16;\n"
                 :: "r"(smem_dst), "l"(gsrc));
}

// ---------------- bf16 GEMM (3-term split) + fused el/er epilogue ----------
__global__ __launch_bounds__(256, 2) void gemm_tc(
    const float* __restrict__ A, const float* __restrict__ W,
    float* __restrict__ Co, int K, int Nn, size_t aSB, size_t aSC,
    const float* __restrict__ al, const float* __restrict__ ar,
    float* __restrict__ elo, float* __restrict__ ero, int Dh) {
    extern __shared__ float sm[];

    int bc = blockIdx.z;
    int b  = bc / C, c = bc % C;
    const float* Ab = A + (size_t)b * aSB + (size_t)c * aSC;
    const float* Wc = W + (size_t)c * K * Nn;
    float*       Cb = Co + (size_t)bc * NN * Nn;

    int m0 = blockIdx.y * 128, n0 = blockIdx.x * 128;
    int tid  = threadIdx.x;
    int lane = tid & 31, warp = tid >> 5;
    int wm = warp & 1, wn = warp >> 1;
    int gr = lane >> 2, tg = lane & 3;

    uint32_t smem_base = (uint32_t)__cvta_generic_to_shared(sm);

    int am0 = tid >> 2,          akq = (tid & 3) * 4;
    int am1 = (tid + 256) >> 2;
    int bk0 = tid >> 5,          bnq = (tid & 31) * 4;
    int bk1 = (tid + 256) >> 5;

    auto issue_stage = [&](int st, int t) {
        uint32_t aB = smem_base + (st * STG) * 4;
        uint32_t bB = smem_base + (st * STG + A_STG) * 4;
        const float* Abt = Ab + (size_t)m0 * K + t * 16;
        cp16(aB + (am0 * AP + akq) * 4, Abt + (size_t)am0 * K + akq);
        cp16(aB + (am1 * AP + akq) * 4, Abt + (size_t)am1 * K + akq);
        const float* Wct = Wc + (size_t)(t * 16) * Nn + n0;
        cp16(bB + (bk0 * BP + bnq) * 4, Wct + (size_t)bk0 * Nn + bnq);
        cp16(bB + (bk1 * BP + bnq) * 4, Wct + (size_t)bk1 * Nn + bnq);
    };

    float acc[4][4][4] = {};

    auto compute_stage = [&](int st) {
        const float* As = sm + st * STG;
        const float* Bs = As + A_STG;
        uint32_t ah[4][4], alo[4][4], bh[4][2], bl[4][2];
#pragma unroll
        for (int mt = 0; mt < 4; mt++) {
            int m = wm * 64 + mt * 16 + gr;
            float2 x0 = *(const float2*)(As + m * AP + 2 * tg);
            float2 x1 = *(const float2*)(As + (m + 8) * AP + 2 * tg);
            float2 x2 = *(const float2*)(As + m * AP + 2 * tg + 8);
            float2 x3 = *(const float2*)(As + (m + 8) * AP + 2 * tg + 8);
            ah[mt][0] = packbf2(x0.y, x0.x);
            ah[mt][1] = packbf2(x1.y, x1.x);
            ah[mt][2] = packbf2(x2.y, x2.x);
            ah[mt][3] = packbf2(x3.y, x3.x);
            alo[mt][0] = packbf2(x0.y - bfhi(ah[mt][0]), x0.x - bflo(ah[mt][0]));
            alo[mt][1] = packbf2(x1.y - bfhi(ah[mt][1]), x1.x - bflo(ah[mt][1]));
            alo[mt][2] = packbf2(x2.y - bfhi(ah[mt][2]), x2.x - bflo(ah[mt][2]));
            alo[mt][3] = packbf2(x3.y - bfhi(ah[mt][3]), x3.x - bflo(ah[mt][3]));
        }
#pragma unroll
        for (int nt = 0; nt < 4; nt++) {
            int n = wn * 32 + nt * 8 + gr;
            const float* wb = Bs + 2 * tg * BP + n;
            float w0 = wb[0], w1 = wb[BP], w2 = wb[8 * BP], w3 = wb[9 * BP];
            bh[nt][0] = packbf2(w1, w0);
            bh[nt][1] = packbf2(w3, w2);
            bl[nt][0] = packbf2(w1 - bfhi(bh[nt][0]), w0 - bflo(bh[nt][0]));
            bl[nt][1] = packbf2(w3 - bfhi(bh[nt][1]), w2 - bflo(bh[nt][1]));
        }
#pragma unroll
        for (int mt = 0; mt < 4; mt++)
#pragma unroll
            for (int nt = 0; nt < 4; nt++) {
                mma_bf16(acc[mt][nt], ah[mt], bh[nt]);
                mma_bf16(acc[mt][nt], alo[mt], bh[nt]);
                mma_bf16(acc[mt][nt], ah[mt], bl[nt]);
            }
    };

    int T = K / 16;
    issue_stage(0, 0);
    asm volatile("cp.async.commit_group;\n" ::);
    issue_stage(1, 1);
    asm volatile("cp.async.commit_group;\n" ::);

    for (int i = 0; i < T; i++) {
        asm volatile("cp.async.wait_group 1;\n" ::);
        __syncthreads();
        if (i + 2 < T) issue_stage((i + 2) % 3, i + 2);
        asm volatile("cp.async.commit_group;\n" ::);
        compute_stage(i % 3);
    }

    // ---- epilogue: store C + fused el/er partials ----
    int head  = (n0 + wn * 32) / Dh;
    int dbase = n0 + wn * 32 - head * Dh;
    const float* alh = al + ((size_t)c * H + head) * Dh;
    const float* arh = ar + ((size_t)c * H + head) * Dh;
    float* elh = elo + ((size_t)bc * H + head) * NN;
    float* erh = ero + ((size_t)bc * H + head) * NN;

#pragma unroll
    for (int mt = 0; mt < 4; mt++) {
        float el0 = 0.f, el1 = 0.f, er0 = 0.f, er1 = 0.f;
#pragma unroll
        for (int nt = 0; nt < 4; nt++) {
            int row = m0 + wm * 64 + mt * 16 + gr;
            int col = n0 + wn * 32 + nt * 8 + tg * 2;
            *(float2*)(Cb + (size_t)row * Nn + col) =
                make_float2(acc[mt][nt][0], acc[mt][nt][1]);
            *(float2*)(Cb + (size_t)(row + 8) * Nn + col) =
                make_float2(acc[mt][nt][2], acc[mt][nt][3]);

            int d = dbase + nt * 8 + tg * 2;
            float a0 = alh[d], a1 = alh[d + 1];
            float r0 = arh[d], r1 = arh[d + 1];
            el0 += acc[mt][nt][0] * a0 + acc[mt][nt][1] * a1;
            el1 += acc[mt][nt][2] * a0 + acc[mt][nt][3] * a1;
            er0 += acc[mt][nt][0] * r0 + acc[mt][nt][1] * r1;
            er1 += acc[mt][nt][2] * r0 + acc[mt][nt][3] * r1;
        }
#pragma unroll
        for (int o = 1; o < 4; o <<= 1) {
            el0 += __shfl_xor_sync(0xffffffffu, el0, o);
            el1 += __shfl_xor_sync(0xffffffffu, el1, o);
            er0 += __shfl_xor_sync(0xffffffffu, er0, o);
            er1 += __shfl_xor_sync(0xffffffffu, er1, o);
        }
        if (tg == 0) {
            int row = m0 + wm * 64 + mt * 16 + gr;
            atomicAdd(elh + row,     el0);
            atomicAdd(elh + row + 8, el1);
            atomicAdd(erh + row,     er0);
            atomicAdd(erh + row + 8, er1);
        }
    }
}

// ================= agg v2 (D=128, JT=128): bf16 (p single + f 2-term) =================
template <bool RELU>
__global__ __launch_bounds__(256, 2) void agg_tc2(
    const float* __restrict__ adj,
    const float* __restrict__ feat,
    const float* __restrict__ el,
    const float* __restrict__ er,
    const float* __restrict__ bias,
    float* __restrict__ out) {
    constexpr int D  = 128, JT = 128;
    constexpr int PP = 132;           // (8tg+gr)%32 conflict-free for k-pair loads
    constexpr int FP = 132;
    constexpr int NSUB = 256 / JT;
    constexpr int ADJ_ST = 16 * JT;
    constexpr int F_ST   = 16 * FP;
    constexpr int P_ST   = 16 * PP;
    constexpr int T = NN / 16;

    extern __shared__ float sm[];
    float* el_s  = sm;
    float* er_s  = el_s + NN;
    float* m_s   = er_s + JT;
    float* sc_s  = m_s + JT;
    float* red   = sc_s + JT;
    float* s_red = red + 8;
    float* adj_s = s_red + NSUB * JT;
    float* f_s   = adj_s + 4 * ADJ_ST;
    float* p_s   = f_s + 4 * F_ST;

    int bc = blockIdx.z, h = blockIdx.y;
    int c = bc % C;
    int j0 = blockIdx.x * JT;
    int tid = threadIdx.x;
    int lane = tid & 31, warp = tid >> 5;
    int jm = warp & 1, dn = warp >> 1;
    int gr = lane >> 2, tg = lane & 3;

    const float* adj_bc = adj + (size_t)bc * NN * NN;
    const float* elh = el + (size_t)(bc * H + h) * NN;
    const float* erh = er + (size_t)(bc * H + h) * NN;
    const float* featb = feat + (size_t)bc * NN * (H * D) + h * D;

    uint32_t smem_u32 = (uint32_t)__cvta_generic_to_shared(sm);
    uint32_t adj_u32  = smem_u32 + (uint32_t)((adj_s - sm) * 4);
    uint32_t f_u32    = smem_u32 + (uint32_t)((f_s - sm) * 4);

    auto issue_stage = [&](int st, int t) {
        uint32_t aB = adj_u32 + st * ADJ_ST * 4;
#pragma unroll
        for (int l = 0; l < (16 * JT / 4) / 256; l++) {
            int s = tid + l * 256;
            int r = s / (JT / 4), cq = s % (JT / 4);
            cp16(aB + (r * JT + cq * 4) * 4,
                 adj_bc + (size_t)(t * 16 + r) * NN + j0 + cq * 4);
        }
        uint32_t fB = f_u32 + st * F_ST * 4;
#pragma unroll
        for (int l = 0; l < (16 * D / 4) / 256; l++) {
            int s = tid + l * 256;
            int r = s / (D / 4), cq = s % (D / 4);
            cp16(fB + (r * FP + cq * 4) * 4,
                 featb + (size_t)(t * 16 + r) * (H * D) + cq * 4);
        }
    };

    float e0 = elh[tid], e1 = elh[tid + 256];
    el_s[tid] = e0; el_s[tid + 256] = e1;
    if (tid < JT) er_s[tid] = erh[j0 + tid];

    issue_stage(0, 0);
    asm volatile("cp.async.commit_group;\n" ::);
    issue_stage(1, 1);
    asm volatile("cp.async.commit_group;\n" ::);
    issue_stage(2, 2);
    asm volatile("cp.async.commit_group;\n" ::);

    float v = fmaxf(e0, e1);
#pragma unroll
    for (int o = 16; o; o >>= 1) v = fmaxf(v, __shfl_xor_sync(0xffffffffu, v, o));
    if (lane == 0) red[warp] = v;
    __syncthreads();
    if (tid == 0) {
        float m = red[0];
#pragma unroll
        for (int w = 1; w < 8; w++) m = fmaxf(m, red[w]);
        red[0] = m;
    }
    __syncthreads();
    if (tid < JT) {
        float e = red[0] + er_s[tid];
        m_s[tid] = e > 0.f ? e : 0.2f * e;
    }

    int pj  = tid % JT;
    int pi0 = tid / JT;
    float s_priv = 0.f;

    // produce p(t), rounded to bf16 (consistent numerator/denominator)
    auto produce = [&](int t) {
        const float* a_st = adj_s + (t % 4) * ADJ_ST;
        float* p_nb = p_s + (t & 1) * P_ST;
#pragma unroll
        for (int q = 0; q < 16 / NSUB; q++) {
            int r = pi0 + q * NSUB;
            float a = a_st[r * JT + pj];
            float pt = 0.f;
            if (a > 0.f) {
                float e = el_s[t * 16 + r] + er_s[pj];
                e = e > 0.f ? e : 0.2f * e;
                float p = __expf(e - m_s[pj]);
                pt = __bfloat162float(__float2bfloat16(p));
                s_priv += pt;
            }
            p_nb[r * PP + pj] = pt;
        }
    };

    asm volatile("cp.async.wait_group 2;\n" ::);
    __syncthreads();
    produce(0);

    float acc[4][4][4] = {};

    for (int i = 0; i < T; i++) {
        asm volatile("cp.async.wait_group 1;\n" ::);
        __syncthreads();

        const float* f_st  = f_s + (i % 4) * F_ST;
        const float* p_buf = p_s + (i & 1) * P_ST;

        uint32_t pa[4][4];
#pragma unroll
        for (int mt = 0; mt < 4; mt++) {
            int jb = jm * 64 + mt * 16 + gr;
            const float* pb = p_buf + 2 * tg * PP + jb;
            pa[mt][0] = packbf2(pb[PP], pb[0]);
            pa[mt][1] = packbf2(pb[PP + 8], pb[8]);
            pa[mt][2] = packbf2(pb[9 * PP], pb[8 * PP]);
            pa[mt][3] = packbf2(pb[9 * PP + 8], pb[8 * PP + 8]);
        }
#pragma unroll
        for (int nt = 0; nt < 4; nt++) {
            int db = dn * 32 + nt * 8 + gr;
            const float* fb = f_st + 2 * tg * FP + db;
            float w0 = fb[0], w1 = fb[FP], w2 = fb[8 * FP], w3 = fb[9 * FP];
            uint32_t bh[2], bl[2];
            bh[0] = packbf2(w1, w0);
            bh[1] = packbf2(w3, w2);
            bl[0] = packbf2(w1 - bfhi(bh[0]), w0 - bflo(bh[0]));
            bl[1] = packbf2(w3 - bfhi(bh[1]), w2 - bflo(bh[1]));
#pragma unroll
            for (int mt = 0; mt < 4; mt++) {
                mma_bf16(acc[mt][nt], pa[mt], bh);
                mma_bf16(acc[mt][nt], pa[mt], bl);
            }
        }

        if (i + 1 < T) produce(i + 1);

        if (i + 3 < T) issue_stage((i + 3) % 4, i + 3);
        asm volatile("cp.async.commit_group;\n" ::);
    }

    s_red[pi0 * JT + pj] = s_priv;
    __syncthreads();
    if (tid < JT)
        sc_s[tid] = 1.0f / fmaxf(s_red[tid] + s_red[JT + tid], 1e-9f);
    __syncthreads();

    const float* bh_ = bias + (size_t)c * (H * D) + h * D;
#pragma unroll
    for (int mt = 0; mt < 4; mt++) {
#pragma unroll
        for (int nt = 0; nt < 4; nt++) {
            int jl = jm * 64 + mt * 16 + gr;
            int d  = dn * 32 + nt * 8 + tg * 2;
            float bb0 = bh_[d], bb1 = bh_[d + 1];
            float sc0 = sc_s[jl], sc1 = sc_s[jl + 8];
            float o0 = acc[mt][nt][0] * sc0 + bb0;
            float o1 = acc[mt][nt][1] * sc0 + bb1;
            float o2 = acc[mt][nt][2] * sc1 + bb0;
            float o3 = acc[mt][nt][3] * sc1 + bb1;
            if (RELU) {
                o0 = fmaxf(o0, 0.f); o1 = fmaxf(o1, 0.f);
                o2 = fmaxf(o2, 0.f); o3 = fmaxf(o3, 0.f);
            }
            int j = j0 + jl;
            *(float2*)(out + ((size_t)bc * NN + j) * (H * D) + h * D + d)     = make_float2(o0, o1);
            *(float2*)(out + ((size_t)bc * NN + j + 8) * (H * D) + h * D + d) = make_float2(o2, o3);
        }
    }
}

constexpr int AGG2_SMEM = (NN + 3 * 128 + 8 + 2 * 128 + 4 * 16 * 128 + 4 * 16 * 132 + 2 * 16 * 132) * 4; // 88096

// ================= agg v1 (layer 2: D=64, JT=256), bf16 =================
template <int D, int JT, bool RELU>
__global__ __launch_bounds__(256) void agg_tc(
    const float* __restrict__ adj,
    const float* __restrict__ feat,
    const float* __restrict__ el,
    const float* __restrict__ er,
    const float* __restrict__ bias,
    float* __restrict__ out) {
    constexpr int PP = JT + 4;        // 260: (8tg+gr)%32 conflict-free
    constexpr int FP = D + 4;         // 68
    constexpr int WJ = JT / 64;
    constexpr int NSUB = 256 / JT;
    constexpr int ADJ_ST = 16 * JT;
    constexpr int F_ST   = 16 * FP;
    constexpr int P_ST   = 16 * PP;

    extern __shared__ float sm[];
    float* el_s  = sm;
    float* er_s  = el_s + NN;
    float* m_s   = er_s + JT;
    float* sc_s  = m_s + JT;
    float* red   = sc_s + JT;
    float* s_red = red + 8;
    float* adj_s = s_red + NSUB * JT;
    float* f_s   = adj_s + 3 * ADJ_ST;
    float* p_s   = f_s + 3 * F_ST;

    int bc = blockIdx.z, h = blockIdx.y;
    int c = bc % C;
    int j0 = blockIdx.x * JT;
    int tid = threadIdx.x;
    int lane = tid & 31, warp = tid >> 5;
    int jm = warp % WJ, dn = warp / WJ;
    int gr = lane >> 2, tg = lane & 3;

    const float* adj_bc = adj + (size_t)bc * NN * NN;
    const float* elh = el + (size_t)(bc * H + h) * NN;
    const float* erh = er + (size_t)(bc * H + h) * NN;
    const float* featb = feat + (size_t)bc * NN * (H * D) + h * D;

    uint32_t smem_u32 = (uint32_t)__cvta_generic_to_shared(sm);
    uint32_t adj_u32  = smem_u32 + (uint32_t)((adj_s - sm) * 4);
    uint32_t f_u32    = smem_u32 + (uint32_t)((f_s - sm) * 4);

    auto issue_stage = [&](int st, int t) {
        uint32_t aB = adj_u32 + st * ADJ_ST * 4;
#pragma unroll
        for (int l = 0; l < (16 * JT / 4) / 256; l++) {
            int s = tid + l * 256;
            int r = s / (JT / 4), cq = s % (JT / 4);
            cp16(aB + (r * JT + cq * 4) * 4,
                 adj_bc + (size_t)(t * 16 + r) * NN + j0 + cq * 4);
        }
        uint32_t fB = f_u32 + st * F_ST * 4;
#pragma unroll
        for (int l = 0; l < (16 * D / 4) / 256; l++) {
            int s = tid + l * 256;
            int r = s / (D / 4), cq = s % (D / 4);
            cp16(fB + (r * FP + cq * 4) * 4,
                 featb + (size_t)(t * 16 + r) * (H * D) + cq * 4);
        }
    };

    float e0 = elh[tid], e1 = elh[tid + 256];
    el_s[tid] = e0; el_s[tid + 256] = e1;
#pragma unroll
    for (int t = tid; t < JT; t += 256) er_s[t] = erh[j0 + t];

    issue_stage(0, 0);
    asm volatile("cp.async.commit_group;\n" ::);
    issue_stage(1, 1);
    asm volatile("cp.async.commit_group;\n" ::);

    float v = fmaxf(e0, e1);
#pragma unroll
    for (int o = 16; o; o >>= 1) v = fmaxf(v, __shfl_xor_sync(0xffffffffu, v, o));
    if (lane == 0) red[warp] = v;
    __syncthreads();
    if (tid == 0) {
        float m = red[0];
#pragma unroll
        for (int w = 1; w < 8; w++) m = fmaxf(m, red[w]);
        red[0] = m;
    }
    __syncthreads();
#pragma unroll
    for (int t = tid; t < JT; t += 256) {
        float e = red[0] + er_s[t];
        m_s[t] = e > 0.f ? e : 0.2f * e;
    }

    int pj  = tid % JT;
    int pi0 = tid / JT;

    float acc[4][4][4] = {};
    float s_priv = 0.f;

    constexpr int T = NN / 16;
    for (int i = 0; i < T; i++) {
        asm volatile("cp.async.wait_group 1;\n" ::);
        __syncthreads();

        const float* a_st = adj_s + (i % 3) * ADJ_ST;
        float* p_buf = p_s + (i & 1) * P_ST;
#pragma unroll
        for (int q = 0; q < 16 / NSUB; q++) {
            int r = pi0 + q * NSUB;
            float a = a_st[r * JT + pj];
            float pt = 0.f;
            if (a > 0.f) {
                float e = el_s[i * 16 + r] + er_s[pj];
                e = e > 0.f ? e : 0.2f * e;
                float p = __expf(e - m_s[pj]);
                pt = __bfloat162float(__float2bfloat16(p));
                s_priv += pt;
            }
            p_buf[r * PP + pj] = pt;
        }
        __syncthreads();

        const float* f_st = f_s + (i % 3) * F_ST;
        uint32_t pa[4][4];
#pragma unroll
        for (int mt = 0; mt < 4; mt++) {
            int jb = jm * 64 + mt * 16 + gr;
            const float* pb = p_buf + 2 * tg * PP + jb;
            pa[mt][0] = packbf2(pb[PP], pb[0]);
            pa[mt][1] = packbf2(pb[PP + 8], pb[8]);
            pa[mt][2] = packbf2(pb[9 * PP], pb[8 * PP]);
            pa[mt][3] = packbf2(pb[9 * PP + 8], pb[8 * PP + 8]);
        }
#pragma unroll
        for (int nt = 0; nt < 4; nt++) {
            int db = dn * 32 + nt * 8 + gr;
            const float* fb = f_st + 2 * tg * FP + db;
            float w0 = fb[0], w1 = fb[FP], w2 = fb[8 * FP], w3 = fb[9 * FP];
            uint32_t bh[2], bl[2];
            bh[0] = packbf2(w1, w0);
            bh[1] = packbf2(w3, w2);
            bl[0] = packbf2(w1 - bfhi(bh[0]), w0 - bflo(bh[0]));
            bl[1] = packbf2(w3 - bfhi(bh[1]), w2 - bflo(bh[1]));
#pragma unroll
            for (int mt = 0; mt < 4; mt++) {
                mma_bf16(acc[mt][nt], pa[mt], bh);
                mma_bf16(acc[mt][nt], pa[mt], bl);
            }
        }

        if (i + 2 < T) issue_stage((i + 2) % 3, i + 2);
        asm volatile("cp.async.commit_group;\n" ::);
    }

    s_red[pi0 * JT + pj] = s_priv;
    __syncthreads();
#pragma unroll
    for (int t = tid; t < JT; t += 256) {
        float sv = s_red[t];
        if (NSUB == 2) sv += s_red[JT + t];
        sc_s[t] = 1.0f / fmaxf(sv, 1e-9f);
    }
    __syncthreads();

    const float* bh_ = bias + (size_t)c * (H * D) + h * D;
#pragma unroll
    for (int mt = 0; mt < 4; mt++) {
#pragma unroll
        for (int nt = 0; nt < 4; nt++) {
            int jl = jm * 64 + mt * 16 + gr;
            int d  = dn * 32 + nt * 8 + tg * 2;
            float bb0 = bh_[d], bb1 = bh_[d + 1];
            float sc0 = sc_s[jl], sc1 = sc_s[jl + 8];
            float o0 = acc[mt][nt][0] * sc0 + bb0;
            float o1 = acc[mt][nt][1] * sc0 + bb1;
            float o2 = acc[mt][nt][2] * sc1 + bb0;
            float o3 = acc[mt][nt][3] * sc1 + bb1;
            if (RELU) {
                o0 = fmaxf(o0, 0.f); o1 = fmaxf(o1, 0.f);
                o2 = fmaxf(o2, 0.f); o3 = fmaxf(o3, 0.f);
            }
            int j = j0 + jl;
            *(float2*)(out + ((size_t)bc * NN + j) * (H * D) + h * D + d)     = make_float2(o0, o1);
            *(float2*)(out + ((size_t)bc * NN + j + 8) * (H * D) + h * D + d) = make_float2(o2, o3);
        }
    }
}

constexpr int agg_smem_bytes(int D, int JT) {
    int FP = D + 4, PP = JT + 4, NSUB = 256 / JT;
    return (NN + 3 * JT + 8 + NSUB * JT + 3 * 16 * JT + 3 * 16 * FP + 2 * 16 * PP) * 4;
}
constexpr int AGG_SMEM_64 = agg_smem_bytes(64, 256);   // 101664

// ---------------- head-mean + channel concat ----------------
__global__ void mean_kernel(const float* __restrict__ in2, float* __restrict__ out) {
    int idx = blockIdx.x * 256 + threadIdx.x;
    if (idx >= B * NN * C * DOUT) return;
    int d = idx % DOUT;
    int c = (idx / DOUT) % C;
    int n = (idx / (DOUT * C)) % NN;
    int b = idx / (DOUT * C * NN);
    const float* p = in2 + ((size_t)(b * C + c) * NN + n) * HD2 + d;
    out[idx] = 0.25f * (p[0] + p[DOUT] + p[2 * DOUT] + p[3 * DOUT]);
}

// ---------------- launch ----------------
extern "C" void kernel_launch(void* const* d_in, const int* in_sizes, int n_in,
                              void* d_out, int out_size) {
    const float* x   = (const float*)d_in[0];
    const float* adj = (const float*)d_in[1];
    const float* W0  = (const float*)d_in[2];
    const float* al0 = (const float*)d_in[3];
    const float* ar0 = (const float*)d_in[4];
    const float* b0  = (const float*)d_in[5];
    const float* W1  = (const float*)d_in[6];
    const float* al1 = (const float*)d_in[7];
    const float* ar1 = (const float*)d_in[8];
    const float* b1  = (const float*)d_in[9];
    const float* W2  = (const float*)d_in[10];
    const float* al2 = (const float*)d_in[11];
    const float* ar2 = (const float*)d_in[12];
    const float* b2  = (const float*)d_in[13];
    float* out = (float*)d_out;

    float *feat, *hbuf, *elr, *out2;
    cudaGetSymbolAddress((void**)&feat, g_feat);
    cudaGetSymbolAddress((void**)&hbuf, g_h);
    cudaGetSymbolAddress((void**)&elr,  g_elr);
    cudaGetSymbolAddress((void**)&out2, g_out2);
    float* el = elr;
    float* er = elr + BC * H * NN;

    dim3 t256(256);
    static int attr_set = 0;
    if (!attr_set) {
        cudaFuncSetAttribute(gemm_tc, cudaFuncAttributeMaxDynamicSharedMemorySize, GEMM_SMEM);
        cudaFuncSetAttribute(agg_tc2<true>,
                             cudaFuncAttributeMaxDynamicSharedMemorySize, AGG2_SMEM);
        cudaFuncSetAttribute(agg_tc<DOUT, 256, false>,
                             cudaFuncAttributeMaxDynamicSharedMemorySize, AGG_SMEM_64);
        attr_set = 1;
    }

    size_t elr_bytes = (size_t)2 * BC * H * NN * sizeof(float);

    // ---- layer 0 ----
    cudaMemsetAsync(elr, 0, elr_bytes);
    gemm_tc<<<dim3(HD / 128, NN / 128, BC), t256, GEMM_SMEM>>>(
        x, W0, feat, FIN, HD, (size_t)C * NN * FIN, 0, al0, ar0, el, er, DHID);
    agg_tc2<true><<<dim3(NN / 128, H, BC), t256, AGG2_SMEM>>>(adj, feat, el, er, b0, hbuf);

    // ---- layer 1 ----
    cudaMemsetAsync(elr, 0, elr_bytes);
    gemm_tc<<<dim3(HD / 128, NN / 128, BC), t256, GEMM_SMEM>>>(
        hbuf, W1, feat, HD, HD, (size_t)C * NN * HD, (size_t)NN * HD, al1, ar1, el, er, DHID);
    agg_tc2<true><<<dim3(NN / 128, H, BC), t256, AGG2_SMEM>>>(adj, feat, el, er, b1, hbuf);

    // ---- layer 2 ----
    cudaMemsetAsync(elr, 0, elr_bytes);
    gemm_tc<<<dim3(HD2 / 128, NN / 128, BC), t256, GEMM_SMEM>>>(
        hbuf, W2, feat, HD, HD2, (size_t)C * NN * HD, (size_t)NN * HD, al2, ar2, el, er, DOUT);
    agg_tc<DOUT, 256, false><<<dim3(NN / 256, H, BC), t256, AGG_SMEM_64>>>(adj, feat, el, er, b2, out2);

    // ---- head mean + concat ----
    mean_kernel<<<(B * NN * C * DOUT + 255) / 256, t256>>>(out2, out);
}

// round 13
// speedup vs baseline: 1.5249x; 1.0988x over previous
#include <cuda_runtime.h>
#include <cuda_bf16.h>
#include <cstdint>

// ---------------- problem constants ----------------
constexpr int B    = 8;
constexpr int C    = 5;
constexpr int NN   = 512;
constexpr int FIN  = 768;
constexpr int H    = 4;
constexpr int DHID = 128;
constexpr int DOUT = 64;
constexpr int HD   = H * DHID;   // 512
constexpr int HD2  = H * DOUT;   // 256
constexpr int BC   = B * C;      // 40

// ---------------- scratch ----------------
__device__ __align__(256) float g_feat[(size_t)BC * NN * HD];
__device__ __align__(256) float g_h   [(size_t)BC * NN * HD];
__device__ __align__(256) float g_out2[(size_t)BC * NN * HD2];
__device__ __align__(256) float g_elr [2 * BC * H * NN];   // [el | er]

// ---------------- gemm smem geometry ----------------
constexpr int AP = 20;            // A pitch (f32 words)
constexpr int BP = 132;           // B pitch: bf16 frag loads (8tg+gr)%32 conflict-free
constexpr int A_STG = 128 * AP;   // 2560
constexpr int B_STG = 16 * BP;    // 2112
constexpr int STG   = A_STG + B_STG;
constexpr int GEMM_SMEM = 3 * STG * 4;   // 56064 B

// ---------------- bf16 helpers ----------------
__device__ __forceinline__ uint32_t packbf2(float hi, float lo) {
    uint32_t d;
    asm("cvt.rn.bf16x2.f32 %0, %1, %2;" : "=r"(d) : "f"(hi), "f"(lo));
    return d;
}
__device__ __forceinline__ float bflo(uint32_t u) { return __uint_as_float(u << 16); }
__device__ __forceinline__ float bfhi(uint32_t u) { return __uint_as_float(u & 0xffff0000u); }

__device__ __forceinline__ void mma_bf16(float* d, const uint32_t* a, const uint32_t* b) {
    asm volatile(
        "mma.sync.aligned.m16n8k16.row.col.f32.bf16.bf16.f32 "
        "{%0,%1,%2,%3}, {%4,%5,%6,%7}, {%8,%9}, {%0,%1,%2,%3};\n"
        : "+f"(d[0]), "+f"(d[1]), "+f"(d[2]), "+f"(d[3])
        : "r"(a[0]), "r"(a[1]), "r"(a[2]), "r"(a[3]), "r"(b[0]), "r"(b[1]));
}

__device__ __forceinline__ void cp16(uint32_t smem_dst, const float* gsrc) {
    asm volatile("cp.async.ca.shared.global [%0], [%1], 16;\n"
                 :: "r"(smem_dst), "l"(gsrc));
}

// ---------------- bf16 GEMM (3-term split, R12-validated) + fused el/er ----------
__global__ __launch_bounds__(256, 2) void gemm_tc(
    const float* __restrict__ A, const float* __restrict__ W,
    float* __restrict__ Co, int K, int Nn, size_t aSB, size_t aSC,
    const float* __restrict__ al, const float* __restrict__ ar,
    float* __restrict__ elo, float* __restrict__ ero, int Dh) {
    extern __shared__ float sm[];

    int bc = blockIdx.z;
    int b  = bc / C, c = bc % C;
    const float* Ab = A + (size_t)b * aSB + (size_t)c * aSC;
    const float* Wc = W + (size_t)c * K * Nn;
    float*       Cb = Co + (size_t)bc * NN * Nn;

    int m0 = blockIdx.y * 128, n0 = blockIdx.x * 128;
    int tid  = threadIdx.x;
    int lane = tid & 31, warp = tid >> 5;
    int wm = warp & 1, wn = warp >> 1;
    int gr = lane >> 2, tg = lane & 3;

    uint32_t smem_base = (uint32_t)__cvta_generic_to_shared(sm);

    int am0 = tid >> 2,          akq = (tid & 3) * 4;
    int am1 = (tid + 256) >> 2;
    int bk0 = tid >> 5,          bnq = (tid & 31) * 4;
    int bk1 = (tid + 256) >> 5;

    auto issue_stage = [&](int st, int t) {
        uint32_t aB = smem_base + (st * STG) * 4;
        uint32_t bB = smem_base + (st * STG + A_STG) * 4;
        const float* Abt = Ab + (size_t)m0 * K + t * 16;
        cp16(aB + (am0 * AP + akq) * 4, Abt + (size_t)am0 * K + akq);
        cp16(aB + (am1 * AP + akq) * 4, Abt + (size_t)am1 * K + akq);
        const float* Wct = Wc + (size_t)(t * 16) * Nn + n0;
        cp16(bB + (bk0 * BP + bnq) * 4, Wct + (size_t)bk0 * Nn + bnq);
        cp16(bB + (bk1 * BP + bnq) * 4, Wct + (size_t)bk1 * Nn + bnq);
    };

    float acc[4][4][4] = {};

    auto compute_stage = [&](int st) {
        const float* As = sm + st * STG;
        const float* Bs = As + A_STG;
        uint32_t ah[4][4], alo[4][4], bh[4][2], bl[4][2];
#pragma unroll
        for (int mt = 0; mt < 4; mt++) {
            int m = wm * 64 + mt * 16 + gr;
            float2 x0 = *(const float2*)(As + m * AP + 2 * tg);
            float2 x1 = *(const float2*)(As + (m + 8) * AP + 2 * tg);
            float2 x2 = *(const float2*)(As + m * AP + 2 * tg + 8);
            float2 x3 = *(const float2*)(As + (m + 8) * AP + 2 * tg + 8);
            ah[mt][0] = packbf2(x0.y, x0.x);
            ah[mt][1] = packbf2(x1.y, x1.x);
            ah[mt][2] = packbf2(x2.y, x2.x);
            ah[mt][3] = packbf2(x3.y, x3.x);
            alo[mt][0] = packbf2(x0.y - bfhi(ah[mt][0]), x0.x - bflo(ah[mt][0]));
            alo[mt][1] = packbf2(x1.y - bfhi(ah[mt][1]), x1.x - bflo(ah[mt][1]));
            alo[mt][2] = packbf2(x2.y - bfhi(ah[mt][2]), x2.x - bflo(ah[mt][2]));
            alo[mt][3] = packbf2(x3.y - bfhi(ah[mt][3]), x3.x - bflo(ah[mt][3]));
        }
#pragma unroll
        for (int nt = 0; nt < 4; nt++) {
            int n = wn * 32 + nt * 8 + gr;
            const float* wb = Bs + 2 * tg * BP + n;
            float w0 = wb[0], w1 = wb[BP], w2 = wb[8 * BP], w3 = wb[9 * BP];
            bh[nt][0] = packbf2(w1, w0);
            bh[nt][1] = packbf2(w3, w2);
            bl[nt][0] = packbf2(w1 - bfhi(bh[nt][0]), w0 - bflo(bh[nt][0]));
            bl[nt][1] = packbf2(w3 - bfhi(bh[nt][1]), w2 - bflo(bh[nt][1]));
        }
#pragma unroll
        for (int mt = 0; mt < 4; mt++)
#pragma unroll
            for (int nt = 0; nt < 4; nt++) {
                mma_bf16(acc[mt][nt], ah[mt], bh[nt]);
                mma_bf16(acc[mt][nt], alo[mt], bh[nt]);
                mma_bf16(acc[mt][nt], ah[mt], bl[nt]);
            }
    };

    int T = K / 16;
    issue_stage(0, 0);
    asm volatile("cp.async.commit_group;\n" ::);
    issue_stage(1, 1);
    asm volatile("cp.async.commit_group;\n" ::);

    for (int i = 0; i < T; i++) {
        asm volatile("cp.async.wait_group 1;\n" ::);
        __syncthreads();
        if (i + 2 < T) issue_stage((i + 2) % 3, i + 2);
        asm volatile("cp.async.commit_group;\n" ::);
        compute_stage(i % 3);
    }

    // ---- epilogue: store C + fused el/er partials ----
    int head  = (n0 + wn * 32) / Dh;
    int dbase = n0 + wn * 32 - head * Dh;
    const float* alh = al + ((size_t)c * H + head) * Dh;
    const float* arh = ar + ((size_t)c * H + head) * Dh;
    float* elh = elo + ((size_t)bc * H + head) * NN;
    float* erh = ero + ((size_t)bc * H + head) * NN;

#pragma unroll
    for (int mt = 0; mt < 4; mt++) {
        float el0 = 0.f, el1 = 0.f, er0 = 0.f, er1 = 0.f;
#pragma unroll
        for (int nt = 0; nt < 4; nt++) {
            int row = m0 + wm * 64 + mt * 16 + gr;
            int col = n0 + wn * 32 + nt * 8 + tg * 2;
            *(float2*)(Cb + (size_t)row * Nn + col) =
                make_float2(acc[mt][nt][0], acc[mt][nt][1]);
            *(float2*)(Cb + (size_t)(row + 8) * Nn + col) =
                make_float2(acc[mt][nt][2], acc[mt][nt][3]);

            int d = dbase + nt * 8 + tg * 2;
            float a0 = alh[d], a1 = alh[d + 1];
            float r0 = arh[d], r1 = arh[d + 1];
            el0 += acc[mt][nt][0] * a0 + acc[mt][nt][1] * a1;
            el1 += acc[mt][nt][2] * a0 + acc[mt][nt][3] * a1;
            er0 += acc[mt][nt][0] * r0 + acc[mt][nt][1] * r1;
            er1 += acc[mt][nt][2] * r0 + acc[mt][nt][3] * r1;
        }
#pragma unroll
        for (int o = 1; o < 4; o <<= 1) {
            el0 += __shfl_xor_sync(0xffffffffu, el0, o);
            el1 += __shfl_xor_sync(0xffffffffu, el1, o);
            er0 += __shfl_xor_sync(0xffffffffu, er0, o);
            er1 += __shfl_xor_sync(0xffffffffu, er1, o);
        }
        if (tg == 0) {
            int row = m0 + wm * 64 + mt * 16 + gr;
            atomicAdd(elh + row,     el0);
            atomicAdd(elh + row + 8, el1);
            atomicAdd(erh + row,     er0);
            atomicAdd(erh + row + 8, er1);
        }
    }
}

// ================= agg v2 (D=128, JT=128): bf16, PRE-PACKED p fragments =================
template <bool RELU>
__global__ __launch_bounds__(256, 2) void agg_tc2(
    const float* __restrict__ adj,
    const float* __restrict__ feat,
    const float* __restrict__ el,
    const float* __restrict__ er,
    const float* __restrict__ bias,
    float* __restrict__ out) {
    constexpr int D  = 128, JT = 128;
    constexpr int PPK = JT + 8;       // packed-p pitch (u32): (8tg+gr)%32 conflict-free
    constexpr int FP = 132;
    constexpr int NSUB = 256 / JT;    // 2
    constexpr int ADJ_ST = 16 * JT;
    constexpr int F_ST   = 16 * FP;
    constexpr int PK_ST  = 8 * PPK;   // 8 k-pair rows
    constexpr int T = NN / 16;

    extern __shared__ float sm[];
    float* el_s  = sm;
    float* er_s  = el_s + NN;
    float* m_s   = er_s + JT;
    float* sc_s  = m_s + JT;
    float* red   = sc_s + JT;
    float* s_red = red + 8;
    float* adj_s = s_red + NSUB * JT;
    float* f_s   = adj_s + 4 * ADJ_ST;
    uint32_t* p_pk = (uint32_t*)(f_s + 4 * F_ST);   // 2 * PK_ST u32

    int bc = blockIdx.z, h = blockIdx.y;
    int c = bc % C;
    int j0 = blockIdx.x * JT;
    int tid = threadIdx.x;
    int lane = tid & 31, warp = tid >> 5;
    int jm = warp & 1, dn = warp >> 1;
    int gr = lane >> 2, tg = lane & 3;

    const float* adj_bc = adj + (size_t)bc * NN * NN;
    const float* elh = el + (size_t)(bc * H + h) * NN;
    const float* erh = er + (size_t)(bc * H + h) * NN;
    const float* featb = feat + (size_t)bc * NN * (H * D) + h * D;

    uint32_t smem_u32 = (uint32_t)__cvta_generic_to_shared(sm);
    uint32_t adj_u32  = smem_u32 + (uint32_t)((adj_s - sm) * 4);
    uint32_t f_u32    = smem_u32 + (uint32_t)((f_s - sm) * 4);

    auto issue_stage = [&](int st, int t) {
        uint32_t aB = adj_u32 + st * ADJ_ST * 4;
#pragma unroll
        for (int l = 0; l < (16 * JT / 4) / 256; l++) {
            int s = tid + l * 256;
            int r = s / (JT / 4), cq = s % (JT / 4);
            cp16(aB + (r * JT + cq * 4) * 4,
                 adj_bc + (size_t)(t * 16 + r) * NN + j0 + cq * 4);
        }
        uint32_t fB = f_u32 + st * F_ST * 4;
#pragma unroll
        for (int l = 0; l < (16 * D / 4) / 256; l++) {
            int s = tid + l * 256;
            int r = s / (D / 4), cq = s % (D / 4);
            cp16(fB + (r * FP + cq * 4) * 4,
                 featb + (size_t)(t * 16 + r) * (H * D) + cq * 4);
        }
    };

    float e0 = elh[tid], e1 = elh[tid + 256];
    el_s[tid] = e0; el_s[tid + 256] = e1;
    if (tid < JT) er_s[tid] = erh[j0 + tid];

    issue_stage(0, 0);
    asm volatile("cp.async.commit_group;\n" ::);
    issue_stage(1, 1);
    asm volatile("cp.async.commit_group;\n" ::);
    issue_stage(2, 2);
    asm volatile("cp.async.commit_group;\n" ::);

    float v = fmaxf(e0, e1);
#pragma unroll
    for (int o = 16; o; o >>= 1) v = fmaxf(v, __shfl_xor_sync(0xffffffffu, v, o));
    if (lane == 0) red[warp] = v;
    __syncthreads();
    if (tid == 0) {
        float m = red[0];
#pragma unroll
        for (int w = 1; w < 8; w++) m = fmaxf(m, red[w]);
        red[0] = m;
    }
    __syncthreads();
    if (tid < JT) {
        float e = red[0] + er_s[tid];
        m_s[tid] = e > 0.f ? e : 0.2f * e;
    }

    int pj  = tid % JT;
    int pi0 = tid / JT;
    float s_priv = 0.f;

    // produce p(t) as packed bf16x2 k-pairs: pk[u][j] = {p[2u+1][j], p[2u][j]}
    auto produce = [&](int t) {
        const float* a_st = adj_s + (t % 4) * ADJ_ST;
        uint32_t* p_nb = p_pk + (t & 1) * PK_ST;
#pragma unroll
        for (int q = 0; q < 4; q++) {
            int u = pi0 * 4 + q;
            float a0 = a_st[(2 * u) * JT + pj];
            float a1 = a_st[(2 * u + 1) * JT + pj];
            float p0 = 0.f, p1 = 0.f;
            if (a0 > 0.f) {
                float e = el_s[t * 16 + 2 * u] + er_s[pj];
                e = e > 0.f ? e : 0.2f * e;
                p0 = __expf(e - m_s[pj]);
            }
            if (a1 > 0.f) {
                float e = el_s[t * 16 + 2 * u + 1] + er_s[pj];
                e = e > 0.f ? e : 0.2f * e;
                p1 = __expf(e - m_s[pj]);
            }
            uint32_t pk = packbf2(p1, p0);
            s_priv += bflo(pk) + bfhi(pk);
            p_nb[u * PPK + pj] = pk;
        }
    };

    asm volatile("cp.async.wait_group 2;\n" ::);
    __syncthreads();
    produce(0);

    float acc[4][4][4] = {};

    for (int i = 0; i < T; i++) {
        asm volatile("cp.async.wait_group 1;\n" ::);
        __syncthreads();

        const float* f_st  = f_s + (i % 4) * F_ST;
        const uint32_t* p_buf = p_pk + (i & 1) * PK_ST;

        uint32_t pa[4][4];
#pragma unroll
        for (int mt = 0; mt < 4; mt++) {
            int jb = jm * 64 + mt * 16 + gr;
            const uint32_t* pb = p_buf + tg * PPK + jb;
            pa[mt][0] = pb[0];
            pa[mt][1] = pb[8];
            pa[mt][2] = pb[4 * PPK];
            pa[mt][3] = pb[4 * PPK + 8];
        }
#pragma unroll
        for (int nt = 0; nt < 4; nt++) {
            int db = dn * 32 + nt * 8 + gr;
            const float* fb = f_st + 2 * tg * FP + db;
            float w0 = fb[0], w1 = fb[FP], w2 = fb[8 * FP], w3 = fb[9 * FP];
            uint32_t bh[2], bl[2];
            bh[0] = packbf2(w1, w0);
            bh[1] = packbf2(w3, w2);
            bl[0] = packbf2(w1 - bfhi(bh[0]), w0 - bflo(bh[0]));
            bl[1] = packbf2(w3 - bfhi(bh[1]), w2 - bflo(bh[1]));
#pragma unroll
            for (int mt = 0; mt < 4; mt++) {
                mma_bf16(acc[mt][nt], pa[mt], bh);
                mma_bf16(acc[mt][nt], pa[mt], bl);
            }
        }

        if (i + 1 < T) produce(i + 1);

        if (i + 3 < T) issue_stage((i + 3) % 4, i + 3);
        asm volatile("cp.async.commit_group;\n" ::);
    }

    s_red[pi0 * JT + pj] = s_priv;
    __syncthreads();
    if (tid < JT)
        sc_s[tid] = 1.0f / fmaxf(s_red[tid] + s_red[JT + tid], 1e-9f);
    __syncthreads();

    const float* bh_ = bias + (size_t)c * (H * D) + h * D;
#pragma unroll
    for (int mt = 0; mt < 4; mt++) {
#pragma unroll
        for (int nt = 0; nt < 4; nt++) {
            int jl = jm * 64 + mt * 16 + gr;
            int d  = dn * 32 + nt * 8 + tg * 2;
            float bb0 = bh_[d], bb1 = bh_[d + 1];
            float sc0 = sc_s[jl], sc1 = sc_s[jl + 8];
            float o0 = acc[mt][nt][0] * sc0 + bb0;
            float o1 = acc[mt][nt][1] * sc0 + bb1;
            float o2 = acc[mt][nt][2] * sc1 + bb0;
            float o3 = acc[mt][nt][3] * sc1 + bb1;
            if (RELU) {
                o0 = fmaxf(o0, 0.f); o1 = fmaxf(o1, 0.f);
                o2 = fmaxf(o2, 0.f); o3 = fmaxf(o3, 0.f);
            }
            int j = j0 + jl;
            *(float2*)(out + ((size_t)bc * NN + j) * (H * D) + h * D + d)     = make_float2(o0, o1);
            *(float2*)(out + ((size_t)bc * NN + j + 8) * (H * D) + h * D + d) = make_float2(o2, o3);
        }
    }
}

constexpr int AGG2_SMEM = (NN + 3 * 128 + 8 + 2 * 128 + 4 * 16 * 128 + 4 * 16 * 132 + 2 * 8 * 136) * 4; // 79904

// ================= agg v1 (layer 2: D=64, JT=256), bf16, pre-packed p =================
template <int D, int JT, bool RELU>
__global__ __launch_bounds__(256) void agg_tc(
    const float* __restrict__ adj,
    const float* __restrict__ feat,
    const float* __restrict__ el,
    const float* __restrict__ er,
    const float* __restrict__ bias,
    float* __restrict__ out) {
    constexpr int PPK = JT + 8;       // 264: (8tg+gr)%32 conflict-free
    constexpr int FP = D + 4;         // 68
    constexpr int WJ = JT / 64;
    constexpr int ADJ_ST = 16 * JT;
    constexpr int F_ST   = 16 * FP;
    constexpr int PK_ST  = 8 * PPK;

    extern __shared__ float sm[];
    float* el_s  = sm;
    float* er_s  = el_s + NN;
    float* m_s   = er_s + JT;
    float* sc_s  = m_s + JT;
    float* red   = sc_s + JT;
    float* s_red = red + 8;
    float* adj_s = s_red + JT;
    float* f_s   = adj_s + 3 * ADJ_ST;
    uint32_t* p_pk = (uint32_t*)(f_s + 3 * F_ST);

    int bc = blockIdx.z, h = blockIdx.y;
    int c = bc % C;
    int j0 = blockIdx.x * JT;
    int tid = threadIdx.x;
    int lane = tid & 31, warp = tid >> 5;
    int jm = warp % WJ, dn = warp / WJ;
    int gr = lane >> 2, tg = lane & 3;

    const float* adj_bc = adj + (size_t)bc * NN * NN;
    const float* elh = el + (size_t)(bc * H + h) * NN;
    const float* erh = er + (size_t)(bc * H + h) * NN;
    const float* featb = feat + (size_t)bc * NN * (H * D) + h * D;

    uint32_t smem_u32 = (uint32_t)__cvta_generic_to_shared(sm);
    uint32_t adj_u32  = smem_u32 + (uint32_t)((adj_s - sm) * 4);
    uint32_t f_u32    = smem_u32 + (uint32_t)((f_s - sm) * 4);

    auto issue_stage = [&](int st, int t) {
        uint32_t aB = adj_u32 + st * ADJ_ST * 4;
#pragma unroll
        for (int l = 0; l < (16 * JT / 4) / 256; l++) {
            int s = tid + l * 256;
            int r = s / (JT / 4), cq = s % (JT / 4);
            cp16(aB + (r * JT + cq * 4) * 4,
                 adj_bc + (size_t)(t * 16 + r) * NN + j0 + cq * 4);
        }
        uint32_t fB = f_u32 + st * F_ST * 4;
#pragma unroll
        for (int l = 0; l < (16 * D / 4) / 256; l++) {
            int s = tid + l * 256;
            int r = s / (D / 4), cq = s % (D / 4);
            cp16(fB + (r * FP + cq * 4) * 4,
                 featb + (size_t)(t * 16 + r) * (H * D) + cq * 4);
        }
    };

    float e0 = elh[tid], e1 = elh[tid + 256];
    el_s[tid] = e0; el_s[tid + 256] = e1;
#pragma unroll
    for (int t = tid; t < JT; t += 256) er_s[t] = erh[j0 + t];

    issue_stage(0, 0);
    asm volatile("cp.async.commit_group;\n" ::);
    issue_stage(1, 1);
    asm volatile("cp.async.commit_group;\n" ::);

    float v = fmaxf(e0, e1);
#pragma unroll
    for (int o = 16; o; o >>= 1) v = fmaxf(v, __shfl_xor_sync(0xffffffffu, v, o));
    if (lane == 0) red[warp] = v;
    __syncthreads();
    if (tid == 0) {
        float m = red[0];
#pragma unroll
        for (int w = 1; w < 8; w++) m = fmaxf(m, red[w]);
        red[0] = m;
    }
    __syncthreads();
#pragma unroll
    for (int t = tid; t < JT; t += 256) {
        float e = red[0] + er_s[t];
        m_s[t] = e > 0.f ? e : 0.2f * e;
    }

    int pj = tid;   // JT == 256

    float acc[4][4][4] = {};
    float s_priv = 0.f;

    constexpr int T = NN / 16;
    for (int i = 0; i < T; i++) {
        asm volatile("cp.async.wait_group 1;\n" ::);
        __syncthreads();

        const float* a_st = adj_s + (i % 3) * ADJ_ST;
        uint32_t* p_buf = p_pk + (i & 1) * PK_ST;
#pragma unroll
        for (int u = 0; u < 8; u++) {
            float a0 = a_st[(2 * u) * JT + pj];
            float a1 = a_st[(2 * u + 1) * JT + pj];
            float p0 = 0.f, p1 = 0.f;
            if (a0 > 0.f) {
                float e = el_s[i * 16 + 2 * u] + er_s[pj];
                e = e > 0.f ? e : 0.2f * e;
                p0 = __expf(e - m_s[pj]);
            }
            if (a1 > 0.f) {
                float e = el_s[i * 16 + 2 * u + 1] + er_s[pj];
                e = e > 0.f ? e : 0.2f * e;
                p1 = __expf(e - m_s[pj]);
            }
            uint32_t pk = packbf2(p1, p0);
            s_priv += bflo(pk) + bfhi(pk);
            p_buf[u * PPK + pj] = pk;
        }
        __syncthreads();

        const float* f_st = f_s + (i % 3) * F_ST;
        uint32_t pa[4][4];
#pragma unroll
        for (int mt = 0; mt < 4; mt++) {
            int jb = jm * 64 + mt * 16 + gr;
            const uint32_t* pb = p_buf + tg * PPK + jb;
            pa[mt][0] = pb[0];
            pa[mt][1] = pb[8];
            pa[mt][2] = pb[4 * PPK];
            pa[mt][3] = pb[4 * PPK + 8];
        }
#pragma unroll
        for (int nt = 0; nt < 4; nt++) {
            int db = dn * 32 + nt * 8 + gr;
            const float* fb = f_st + 2 * tg * FP + db;
            float w0 = fb[0], w1 = fb[FP], w2 = fb[8 * FP], w3 = fb[9 * FP];
            uint32_t bh[2], bl[2];
            bh[0] = packbf2(w1, w0);
            bh[1] = packbf2(w3, w2);
            bl[0] = packbf2(w1 - bfhi(bh[0]), w0 - bflo(bh[0]));
            bl[1] = packbf2(w3 - bfhi(bh[1]), w2 - bflo(bh[1]));
#pragma unroll
            for (int mt = 0; mt < 4; mt++) {
                mma_bf16(acc[mt][nt], pa[mt], bh);
                mma_bf16(acc[mt][nt], pa[mt], bl);
            }
        }

        if (i + 2 < T) issue_stage((i + 2) % 3, i + 2);
        asm volatile("cp.async.commit_group;\n" ::);
    }

    s_red[pj] = s_priv;
    __syncthreads();
#pragma unroll
    for (int t = tid; t < JT; t += 256)
        sc_s[t] = 1.0f / fmaxf(s_red[t], 1e-9f);
    __syncthreads();

    const float* bh_ = bias + (size_t)c * (H * D) + h * D;
#pragma unroll
    for (int mt = 0; mt < 4; mt++) {
#pragma unroll
        for (int nt = 0; nt < 4; nt++) {
            int jl = jm * 64 + mt * 16 + gr;
            int d  = dn * 32 + nt * 8 + tg * 2;
            float bb0 = bh_[d], bb1 = bh_[d + 1];
            float sc0 = sc_s[jl], sc1 = sc_s[jl + 8];
            float o0 = acc[mt][nt][0] * sc0 + bb0;
            float o1 = acc[mt][nt][1] * sc0 + bb1;
            float o2 = acc[mt][nt][2] * sc1 + bb0;
            float o3 = acc[mt][nt][3] * sc1 + bb1;
            if (RELU) {
                o0 = fmaxf(o0, 0.f); o1 = fmaxf(o1, 0.f);
                o2 = fmaxf(o2, 0.f); o3 = fmaxf(o3, 0.f);
            }
            int j = j0 + jl;
            *(float2*)(out + ((size_t)bc * NN + j) * (H * D) + h * D + d)     = make_float2(o0, o1);
            *(float2*)(out + ((size_t)bc * NN + j + 8) * (H * D) + h * D + d) = make_float2(o2, o3);
        }
    }
}

constexpr int AGG_SMEM_64 =
    (NN + 3 * 256 + 8 + 256 + 3 * 16 * 256 + 3 * 16 * 68 + 2 * 8 * 264) * 4;  // 85280

// ---------------- head-mean + channel concat ----------------
__global__ void mean_kernel(const float* __restrict__ in2, float* __restrict__ out) {
    int idx = blockIdx.x * 256 + threadIdx.x;
    if (idx >= B * NN * C * DOUT) return;
    int d = idx % DOUT;
    int c = (idx / DOUT) % C;
    int n = (idx / (DOUT * C)) % NN;
    int b = idx / (DOUT * C * NN);
    const float* p = in2 + ((size_t)(b * C + c) * NN + n) * HD2 + d;
    out[idx] = 0.25f * (p[0] + p[DOUT] + p[2 * DOUT] + p[3 * DOUT]);
}

// ---------------- launch ----------------
extern "C" void kernel_launch(void* const* d_in, const int* in_sizes, int n_in,
                              void* d_out, int out_size) {
    const float* x   = (const float*)d_in[0];
    const float* adj = (const float*)d_in[1];
    const float* W0  = (const float*)d_in[2];
    const float* al0 = (const float*)d_in[3];
    const float* ar0 = (const float*)d_in[4];
    const float* b0  = (const float*)d_in[5];
    const float* W1  = (const float*)d_in[6];
    const float* al1 = (const float*)d_in[7];
    const float* ar1 = (const float*)d_in[8];
    const float* b1  = (const float*)d_in[9];
    const float* W2  = (const float*)d_in[10];
    const float* al2 = (const float*)d_in[11];
    const float* ar2 = (const float*)d_in[12];
    const float* b2  = (const float*)d_in[13];
    float* out = (float*)d_out;

    float *feat, *hbuf, *elr, *out2;
    cudaGetSymbolAddress((void**)&feat, g_feat);
    cudaGetSymbolAddress((void**)&hbuf, g_h);
    cudaGetSymbolAddress((void**)&elr,  g_elr);
    cudaGetSymbolAddress((void**)&out2, g_out2);
    float* el = elr;
    float* er = elr + BC * H * NN;

    dim3 t256(256);
    static int attr_set = 0;
    if (!attr_set) {
        cudaFuncSetAttribute(gemm_tc, cudaFuncAttributeMaxDynamicSharedMemorySize, GEMM_SMEM);
        cudaFuncSetAttribute(agg_tc2<true>,
                             cudaFuncAttributeMaxDynamicSharedMemorySize, AGG2_SMEM);
        cudaFuncSetAttribute(agg_tc<DOUT, 256, false>,
                             cudaFuncAttributeMaxDynamicSharedMemorySize, AGG_SMEM_64);
        attr_set = 1;
    }

    size_t elr_bytes = (size_t)2 * BC * H * NN * sizeof(float);

    // ---- layer 0 ----
    cudaMemsetAsync(elr, 0, elr_bytes);
    gemm_tc<<<dim3(HD / 128, NN / 128, BC), t256, GEMM_SMEM>>>(
        x, W0, feat, FIN, HD, (size_t)C * NN * FIN, 0, al0, ar0, el, er, DHID);
    agg_tc2<true><<<dim3(NN / 128, H, BC), t256, AGG2_SMEM>>>(adj, feat, el, er, b0, hbuf);

    // ---- layer 1 ----
    cudaMemsetAsync(elr, 0, elr_bytes);
    gemm_tc<<<dim3(HD / 128, NN / 128, BC), t256, GEMM_SMEM>>>(
        hbuf, W1, feat, HD, HD, (size_t)C * NN * HD, (size_t)NN * HD, al1, ar1, el, er, DHID);
    agg_tc2<true><<<dim3(NN / 128, H, BC), t256, AGG2_SMEM>>>(adj, feat, el, er, b1, hbuf);

    // ---- layer 2 ----
    cudaMemsetAsync(elr, 0, elr_bytes);
    gemm_tc<<<dim3(HD2 / 128, NN / 128, BC), t256, GEMM_SMEM>>>(
        hbuf, W2, feat, HD, HD2, (size_t)C * NN * HD, (size_t)NN * HD, al2, ar2, el, er, DOUT);
    agg_tc<DOUT, 256, false><<<dim3(NN / 256, H, BC), t256, AGG_SMEM_64>>>(adj, feat, el, er, b2, out2);

    // ---- head mean + concat ----
    mean_kernel<<<(B * NN * C * DOUT + 255) / 256, t256>>>(out2, out);
}